// round 12
// baseline (speedup 1.0000x reference)
#include <cuda_runtime.h>
#include <cstdint>

#define WIN_N   49
#define DIMC    384
#define NHEAD   12
#define HD      32
#define BWIN    4096
#define MROWS   (BWIN * WIN_N)      /* 200704 */
#define QKV_N   (3 * DIMC)          /* 1152   */

#define QK_SCALE 0.17677669529663687f   /* 32^-0.5 */

#define BK      32                  /* K per pipeline chunk */
#define NCHUNK  (DIMC / BK)         /* 12 */
#define SPAD    36                  /* smem row stride in floats (conflict-free frags) */
#define STAGE_FLOATS (2 * 128 * SPAD)          /* A tile + B tile per stage = 9216 */
#define SMEM_DYN (2 * STAGE_FLOATS * 4)        /* 73728 B, double buffered */

/* attention smem layout (floats) */
#define AQS     36                  /* q/k row stride */
#define AVS     60                  /* v^T / P row stride */
#define OFF_QH  0
#define OFF_QL  (OFF_QH + 64 * AQS)
#define OFF_KH  (OFF_QL + 64 * AQS)
#define OFF_KL  (OFF_KH + 64 * AQS)
#define OFF_VTH (OFF_KL + 64 * AQS)
#define OFF_VTL (OFF_VTH + 32 * AVS)
#define OFF_PH  (OFF_VTL + 32 * AVS)
#define OFF_PL  (OFF_PH + 64 * AVS)
#define ATT_FLOATS (OFF_PL + 64 * AVS)          /* 20736 floats = 82944 B */
#define SMEM_ATT (ATT_FLOATS * 4)

/* -------- scratch: static device globals (allocation-free per harness rules) -------- */
__device__ __align__(256) float g_qkv[(size_t)MROWS * QKV_N];   /* fp32 q|k|v (q pre-scaled) */
__device__ __align__(256) float g_ctx[(size_t)MROWS * DIMC];    /* attention out, tf32-rounded */
__device__ __align__(256) float g_bias[NHEAD * WIN_N * WIN_N];  /* gathered rel-pos bias */
__device__ __align__(256) float g_xt [(size_t)MROWS * DIMC];    /* x,  tf32-rounded */
__device__ __align__(256) float g_wqt[QKV_N * DIMC];            /* qkv_w, tf32-rounded */
__device__ __align__(256) float g_wpt[DIMC * DIMC];             /* proj_w, tf32-rounded */

/* ======================= helpers (all plain sm_80+ PTX) ======================= */
__device__ __forceinline__ uint32_t f2tf32(float x) {
    uint32_t r; asm("cvt.rna.tf32.f32 %0, %1;" : "=r"(r) : "f"(x)); return r;
}
__device__ __forceinline__ float tf32r(float x) { return __uint_as_float(f2tf32(x)); }

__device__ __forceinline__ void cp16(float* dst_smem, const float* src_gmem) {
    uint32_t d = (uint32_t)__cvta_generic_to_shared(dst_smem);
    asm volatile("cp.async.cg.shared.global [%0], [%1], 16;" :: "r"(d), "l"(src_gmem) : "memory");
}
__device__ __forceinline__ void cp_commit() {
    asm volatile("cp.async.commit_group;" ::: "memory");
}
__device__ __forceinline__ void cp_wait0() {
    asm volatile("cp.async.wait_group 0;" ::: "memory");
}
__device__ __forceinline__ void mma8(float* c, const uint32_t* a, uint32_t b0, uint32_t b1) {
    asm volatile(
        "mma.sync.aligned.m16n8k8.row.col.f32.tf32.tf32.f32 "
        "{%0,%1,%2,%3}, {%4,%5,%6,%7}, {%8,%9}, {%0,%1,%2,%3};"
        : "+f"(c[0]), "+f"(c[1]), "+f"(c[2]), "+f"(c[3])
        : "r"(a[0]), "r"(a[1]), "r"(a[2]), "r"(a[3]), "r"(b0), "r"(b1));
}

/* ============================================================================
 * Tensor-core GEMM via portable mma.sync (tf32, fp32 accum)  [unchanged R10]
 * ==========================================================================*/
template<int N, bool SCALE_Q>
__global__ void __launch_bounds__(128)
gemm_mma(const float* __restrict__ A, const float* __restrict__ W,
         const float* __restrict__ bias, float* __restrict__ C)
{
    extern __shared__ __align__(16) float dsm[];
    const int tid  = threadIdx.x;
    const int m0   = blockIdx.y * 128;
    const int n0   = blockIdx.x * 128;
    const int wid  = tid >> 5, lane = tid & 31;
    const int wm   = wid >> 1, wn = wid & 1;
    const int grp  = lane >> 2, sub = lane & 3;

    float acc[4][8][4];
    #pragma unroll
    for (int mt = 0; mt < 4; mt++)
        #pragma unroll
        for (int nt = 0; nt < 8; nt++)
            #pragma unroll
            for (int r = 0; r < 4; r++) acc[mt][nt][r] = 0.f;

    auto prefetch = [&](int kc, int buf) {
        float* As = dsm + buf * STAGE_FLOATS;
        float* Bs = As + 128 * SPAD;
        const int k0 = kc * BK;
        #pragma unroll
        for (int i = 0; i < 8; i++) {
            const int idx = tid + i * 128;
            const int r = idx >> 3, q = idx & 7;
            cp16(As + r * SPAD + q * 4, A + (size_t)(m0 + r) * DIMC + k0 + q * 4);
            cp16(Bs + r * SPAD + q * 4, W + (size_t)(n0 + r) * DIMC + k0 + q * 4);
        }
        cp_commit();
    };

    prefetch(0, 0);

    for (int kc = 0; kc < NCHUNK; kc++) {
        cp_wait0();
        __syncthreads();
        if (kc + 1 < NCHUNK) prefetch(kc + 1, (kc + 1) & 1);

        const uint32_t* As = (const uint32_t*)(dsm + (kc & 1) * STAGE_FLOATS);
        const uint32_t* Bs = As + 128 * SPAD;

        #pragma unroll
        for (int ks = 0; ks < 4; ks++) {
            const int k0 = ks * 8;
            uint32_t a[4][4];
            #pragma unroll
            for (int mt = 0; mt < 4; mt++) {
                const uint32_t* p = As + (wm * 64 + mt * 16 + grp) * SPAD + k0 + sub;
                a[mt][0] = p[0];
                a[mt][1] = p[8 * SPAD];
                a[mt][2] = p[4];
                a[mt][3] = p[8 * SPAD + 4];
            }
            #pragma unroll
            for (int nt = 0; nt < 8; nt++) {
                const uint32_t* p = Bs + (wn * 64 + nt * 8 + grp) * SPAD + k0 + sub;
                const uint32_t b0 = p[0], b1 = p[4];
                #pragma unroll
                for (int mt = 0; mt < 4; mt++)
                    mma8(acc[mt][nt], a[mt], b0, b1);
            }
        }
        __syncthreads();
    }

    const bool do_scale = SCALE_Q && (n0 < DIMC);
    #pragma unroll
    for (int mt = 0; mt < 4; mt++) {
        const int r0 = m0 + wm * 64 + mt * 16 + grp;
        #pragma unroll
        for (int nt = 0; nt < 8; nt++) {
            const int col = n0 + wn * 64 + nt * 8 + 2 * sub;
            const float2 bv = *reinterpret_cast<const float2*>(&bias[col]);
            float2 o0 = make_float2(acc[mt][nt][0] + bv.x, acc[mt][nt][1] + bv.y);
            float2 o1 = make_float2(acc[mt][nt][2] + bv.x, acc[mt][nt][3] + bv.y);
            if (do_scale) {
                o0.x *= QK_SCALE; o0.y *= QK_SCALE;
                o1.x *= QK_SCALE; o1.y *= QK_SCALE;
            }
            *reinterpret_cast<float2*>(&C[(size_t)r0 * N + col])       = o0;
            *reinterpret_cast<float2*>(&C[(size_t)(r0 + 8) * N + col]) = o1;
        }
    }
}

/* ============================================================================ */
__global__ void cvt_tf32(const float4* __restrict__ src, float4* __restrict__ dst, int n4)
{
    const int i = blockIdx.x * blockDim.x + threadIdx.x;
    if (i < n4) {
        float4 v = src[i];
        v.x = tf32r(v.x); v.y = tf32r(v.y); v.z = tf32r(v.z); v.w = tf32r(v.w);
        dst[i] = v;
    }
}

__global__ void bias_gather(const float* __restrict__ bias_table,
                            const int* __restrict__ rel_index)
{
    const int h = blockIdx.x;
    for (int idx = threadIdx.x; idx < WIN_N * WIN_N; idx += blockDim.x)
        g_bias[h * WIN_N * WIN_N + idx] = bias_table[rel_index[idx] * NHEAD + h];
}

/* ============================================================================
 * Windowed attention via split-tf32 mma.sync.
 * One block (128 thr, 4 warps) per (head h, window b).
 * QK^T:  qh*kh + qh*kl + ql*kh  (error-compensated; ~fp32-accurate)
 * PV:    ph*vh + ph*vl + pl*vh
 * Softmax entirely in registers (quad shfl reductions).
 * Rows padded 49->64 (zeros); padded logit cols masked to -1e30 -> p=0.
 * ==========================================================================*/
__global__ void __launch_bounds__(128)
win_attn()
{
    extern __shared__ __align__(16) float sm[];
    float* qh  = sm + OFF_QH;  float* ql  = sm + OFF_QL;
    float* kh  = sm + OFF_KH;  float* kl  = sm + OFF_KL;
    float* vth = sm + OFF_VTH; float* vtl = sm + OFF_VTL;
    float* ph  = sm + OFF_PH;  float* pl  = sm + OFF_PL;

    const int h = blockIdx.x;
    const int b = blockIdx.y;
    const int tid = threadIdx.x;
    const int wid = tid >> 5, lane = tid & 31;
    const int grp = lane >> 2, sub = lane & 3;

    /* ---- load q/k/v (rows padded to 64 with zeros), split into tf32 hi/lo ---- */
    const float* base = g_qkv + (size_t)b * WIN_N * QKV_N + h * HD;
    #pragma unroll
    for (int i = 0; i < 16; i++) {
        const int idx = tid + i * 128;          /* 0..2047 */
        const int r = idx >> 5, d = idx & 31;
        float qv = 0.f, kv = 0.f, vv = 0.f;
        if (r < WIN_N) {
            const float* p = base + (size_t)r * QKV_N + d;
            qv = p[0]; kv = p[DIMC]; vv = p[2 * DIMC];
        }
        const float qh_ = tf32r(qv), kh_ = tf32r(kv);
        qh[r * AQS + d] = qh_;  ql[r * AQS + d] = tf32r(qv - qh_);
        kh[r * AQS + d] = kh_;  kl[r * AQS + d] = tf32r(kv - kh_);
        if (r < 56) {                            /* v^T cols 0..55 (pad zeros) */
            const float vh_ = tf32r(vv);
            vth[d * AVS + r] = vh_;  vtl[d * AVS + r] = tf32r(vv - vh_);
        }
    }
    __syncthreads();

    /* ---- QK^T: warp w -> logits rows 16w..16w+15, cols 0..55 ---- */
    const int r0 = wid * 16;
    const int ra = r0 + grp, rb = ra + 8;
    float acc[7][4];
    #pragma unroll
    for (int nt = 0; nt < 7; nt++)
        #pragma unroll
        for (int r = 0; r < 4; r++) acc[nt][r] = 0.f;

    #pragma unroll
    for (int ks = 0; ks < 4; ks++) {
        const int k0 = ks * 8;
        uint32_t ah[4], al[4];
        {
            const uint32_t* pH = (const uint32_t*)qh + ra * AQS + k0 + sub;
            const uint32_t* pL = (const uint32_t*)ql + ra * AQS + k0 + sub;
            ah[0] = pH[0]; ah[1] = pH[8 * AQS]; ah[2] = pH[4]; ah[3] = pH[8 * AQS + 4];
            al[0] = pL[0]; al[1] = pL[8 * AQS]; al[2] = pL[4]; al[3] = pL[8 * AQS + 4];
        }
        #pragma unroll
        for (int nt = 0; nt < 7; nt++) {
            const uint32_t* bH = (const uint32_t*)kh + (nt * 8 + grp) * AQS + k0 + sub;
            const uint32_t* bL = (const uint32_t*)kl + (nt * 8 + grp) * AQS + k0 + sub;
            const uint32_t bh0 = bH[0], bh1 = bH[4];
            const uint32_t bl0 = bL[0], bl1 = bL[4];
            mma8(acc[nt], ah, bh0, bh1);
            mma8(acc[nt], ah, bl0, bl1);
            mma8(acc[nt], al, bh0, bh1);
        }
    }

    /* ---- bias add + column mask ---- */
    const float* bsrc = g_bias + h * WIN_N * WIN_N;
    #pragma unroll
    for (int nt = 0; nt < 7; nt++) {
        const int c = 8 * nt + 2 * sub;
        if (c < WIN_N) {
            if (ra < WIN_N) acc[nt][0] += bsrc[ra * WIN_N + c];
            if (rb < WIN_N) acc[nt][2] += bsrc[rb * WIN_N + c];
        } else { acc[nt][0] = -1e30f; acc[nt][2] = -1e30f; }
        if (c + 1 < WIN_N) {
            if (ra < WIN_N) acc[nt][1] += bsrc[ra * WIN_N + c + 1];
            if (rb < WIN_N) acc[nt][3] += bsrc[rb * WIN_N + c + 1];
        } else { acc[nt][1] = -1e30f; acc[nt][3] = -1e30f; }
    }

    /* ---- softmax in registers: rows ra ([0],[1]) and rb ([2],[3]) ---- */
    float mx0 = -1e30f, mx1 = -1e30f;
    #pragma unroll
    for (int nt = 0; nt < 7; nt++) {
        mx0 = fmaxf(mx0, fmaxf(acc[nt][0], acc[nt][1]));
        mx1 = fmaxf(mx1, fmaxf(acc[nt][2], acc[nt][3]));
    }
    mx0 = fmaxf(mx0, __shfl_xor_sync(0xffffffffu, mx0, 1));
    mx0 = fmaxf(mx0, __shfl_xor_sync(0xffffffffu, mx0, 2));
    mx1 = fmaxf(mx1, __shfl_xor_sync(0xffffffffu, mx1, 1));
    mx1 = fmaxf(mx1, __shfl_xor_sync(0xffffffffu, mx1, 2));
    float s0 = 0.f, s1 = 0.f;
    #pragma unroll
    for (int nt = 0; nt < 7; nt++) {
        acc[nt][0] = __expf(acc[nt][0] - mx0);
        acc[nt][1] = __expf(acc[nt][1] - mx0);
        acc[nt][2] = __expf(acc[nt][2] - mx1);
        acc[nt][3] = __expf(acc[nt][3] - mx1);
        s0 += acc[nt][0] + acc[nt][1];
        s1 += acc[nt][2] + acc[nt][3];
    }
    s0 += __shfl_xor_sync(0xffffffffu, s0, 1);
    s0 += __shfl_xor_sync(0xffffffffu, s0, 2);
    s1 += __shfl_xor_sync(0xffffffffu, s1, 1);
    s1 += __shfl_xor_sync(0xffffffffu, s1, 2);
    const float i0 = 1.f / s0, i1 = 1.f / s1;

    /* ---- store P split to smem (rows 16w..16w+15, cols 0..55) ---- */
    #pragma unroll
    for (int nt = 0; nt < 7; nt++) {
        const int c = 8 * nt + 2 * sub;
        const float p00 = acc[nt][0] * i0, p01 = acc[nt][1] * i0;
        const float p10 = acc[nt][2] * i1, p11 = acc[nt][3] * i1;
        float hv;
        hv = tf32r(p00); ph[ra * AVS + c]     = hv; pl[ra * AVS + c]     = tf32r(p00 - hv);
        hv = tf32r(p01); ph[ra * AVS + c + 1] = hv; pl[ra * AVS + c + 1] = tf32r(p01 - hv);
        hv = tf32r(p10); ph[rb * AVS + c]     = hv; pl[rb * AVS + c]     = tf32r(p10 - hv);
        hv = tf32r(p11); ph[rb * AVS + c + 1] = hv; pl[rb * AVS + c + 1] = tf32r(p11 - hv);
    }
    __syncwarp();   /* each warp reads back only its own 16 P rows */

    /* ---- PV: out rows 16w..16w+15, cols d 0..31, K = 56 ---- */
    float o[4][4];
    #pragma unroll
    for (int nt = 0; nt < 4; nt++)
        #pragma unroll
        for (int r = 0; r < 4; r++) o[nt][r] = 0.f;

    #pragma unroll
    for (int kb = 0; kb < 7; kb++) {
        const int k0 = kb * 8;
        uint32_t ah[4], al[4];
        {
            const uint32_t* pH = (const uint32_t*)ph + ra * AVS + k0 + sub;
            const uint32_t* pL = (const uint32_t*)pl + ra * AVS + k0 + sub;
            ah[0] = pH[0]; ah[1] = pH[8 * AVS]; ah[2] = pH[4]; ah[3] = pH[8 * AVS + 4];
            al[0] = pL[0]; al[1] = pL[8 * AVS]; al[2] = pL[4]; al[3] = pL[8 * AVS + 4];
        }
        #pragma unroll
        for (int nt = 0; nt < 4; nt++) {
            const uint32_t* bH = (const uint32_t*)vth + (nt * 8 + grp) * AVS + k0 + sub;
            const uint32_t* bL = (const uint32_t*)vtl + (nt * 8 + grp) * AVS + k0 + sub;
            const uint32_t bh0 = bH[0], bh1 = bH[4];
            const uint32_t bl0 = bL[0], bl1 = bL[4];
            mma8(o[nt], ah, bh0, bh1);
            mma8(o[nt], ah, bl0, bl1);
            mma8(o[nt], al, bh0, bh1);
        }
    }

    /* ---- store ctx (tf32-rounded for the proj GEMM's cp.async feed) ---- */
    float* ctx = g_ctx + (size_t)b * WIN_N * DIMC + h * HD;
    #pragma unroll
    for (int nt = 0; nt < 4; nt++) {
        const int d0 = 8 * nt + 2 * sub;
        if (ra < WIN_N)
            *reinterpret_cast<float2*>(&ctx[(size_t)ra * DIMC + d0]) =
                make_float2(tf32r(o[nt][0]), tf32r(o[nt][1]));
        if (rb < WIN_N)
            *reinterpret_cast<float2*>(&ctx[(size_t)rb * DIMC + d0]) =
                make_float2(tf32r(o[nt][2]), tf32r(o[nt][3]));
    }
}

/* ============================================================================ */
extern "C" void kernel_launch(void* const* d_in, const int* in_sizes, int n_in,
                              void* d_out, int out_size)
{
    const float* x          = (const float*)d_in[0];
    const float* qkv_w      = (const float*)d_in[1];
    const float* qkv_b      = (const float*)d_in[2];
    const float* proj_w     = (const float*)d_in[3];
    const float* proj_b     = (const float*)d_in[4];
    const float* bias_table = (const float*)d_in[5];
    const int*   rel_index  = (const int*)d_in[6];
    float*       out        = (float*)d_out;

    float *qkv_ptr, *ctx_ptr, *xt_ptr, *wqt_ptr, *wpt_ptr;
    cudaGetSymbolAddress((void**)&qkv_ptr, g_qkv);
    cudaGetSymbolAddress((void**)&ctx_ptr, g_ctx);
    cudaGetSymbolAddress((void**)&xt_ptr,  g_xt);
    cudaGetSymbolAddress((void**)&wqt_ptr, g_wqt);
    cudaGetSymbolAddress((void**)&wpt_ptr, g_wpt);

    cudaFuncSetAttribute(gemm_mma<QKV_N, true>, cudaFuncAttributeMaxDynamicSharedMemorySize, SMEM_DYN);
    cudaFuncSetAttribute(gemm_mma<DIMC, false>, cudaFuncAttributeMaxDynamicSharedMemorySize, SMEM_DYN);
    cudaFuncSetAttribute(win_attn,              cudaFuncAttributeMaxDynamicSharedMemorySize, SMEM_ATT);

    /* 0) tf32 pre-round of GEMM operands + bias gather */
    {
        const int nx = MROWS * DIMC / 4;
        cvt_tf32<<<(nx + 255) / 256, 256>>>((const float4*)x, (float4*)xt_ptr, nx);
        const int nq = QKV_N * DIMC / 4;
        cvt_tf32<<<(nq + 255) / 256, 256>>>((const float4*)qkv_w, (float4*)wqt_ptr, nq);
        const int np = DIMC * DIMC / 4;
        cvt_tf32<<<(np + 255) / 256, 256>>>((const float4*)proj_w, (float4*)wpt_ptr, np);
        bias_gather<<<NHEAD, 256>>>(bias_table, rel_index);
    }

    /* 1) QKV = X * Wqkv^T + b (q pre-scaled), tf32 mma.sync */
    dim3 g1(QKV_N / 128, MROWS / 128);   /* (9, 1568) */
    gemm_mma<QKV_N, true><<<g1, 128, SMEM_DYN>>>(xt_ptr, wqt_ptr, qkv_b, qkv_ptr);

    /* 2) windowed attention, split-tf32 mma.sync */
    dim3 g2(NHEAD, BWIN);                /* (12, 4096) */
    win_attn<<<g2, 128, SMEM_ATT>>>();

    /* 3) OUT = CTX * Wproj^T + b, tf32 mma.sync */
    dim3 g3(DIMC / 128, MROWS / 128);    /* (3, 1568) */
    gemm_mma<DIMC, false><<<g3, 128, SMEM_DYN>>>(ctx_ptr, wpt_ptr, proj_b, out);
}

// round 13
// speedup vs baseline: 1.6851x; 1.6851x over previous
#include <cuda_runtime.h>
#include <cuda_fp16.h>
#include <cstdint>

#define WIN_N   49
#define DIMC    384
#define NHEAD   12
#define HD      32
#define BWIN    4096
#define MROWS   (BWIN * WIN_N)      /* 200704 */
#define QKV_N   (3 * DIMC)          /* 1152   */

#define QK_SCALE 0.17677669529663687f   /* 32^-0.5 */

/* ---- fp16 GEMM staging ---- */
#define BK      32                  /* K halves per pipeline chunk (64 B/row) */
#define NCHUNK  (DIMC / BK)         /* 12 */
#define SPADH   40                  /* smem row stride in halves: banks (20g+s) conflict-free */
#define STAGE_HALFS (2 * 128 * SPADH)          /* A + B tile per stage = 10240 halves */
#define SMEM_DYN (2 * STAGE_HALFS * 2)         /* 40960 B double buffered */

/* ---- attention smem (halves) ---- */
#define AQH     40                  /* q/k row stride (64 x 32) */
#define AVH     72                  /* vt (32 x 64) / P (64 x 64) row stride */
#define OFF_QH  0
#define OFF_QL  (OFF_QH + 64 * AQH)
#define OFF_KH  (OFF_QL + 64 * AQH)
#define OFF_KL  (OFF_KH + 64 * AQH)
#define OFF_VTH (OFF_KL + 64 * AQH)
#define OFF_VTL (OFF_VTH + 32 * AVH)
#define OFF_PH  (OFF_VTL + 32 * AVH)
#define OFF_PL  (OFF_PH + 64 * AVH)
#define ATT_HALFS (OFF_PL + 64 * AVH)          /* 24064 halves */
#define SMEM_ATT (ATT_HALFS * 2)               /* 48128 B */

/* -------- scratch: static device globals -------- */
__device__ __align__(256) float  g_qkv[(size_t)MROWS * QKV_N];  /* fp32 q|k|v (q pre-scaled) */
__device__ __align__(256) __half g_ctx[(size_t)MROWS * DIMC];   /* attention out (half) */
__device__ __align__(256) float  g_bias[NHEAD * WIN_N * WIN_N]; /* gathered rel-pos bias */
__device__ __align__(256) __half g_xh [(size_t)MROWS * DIMC];   /* x -> half */
__device__ __align__(256) __half g_wqh[QKV_N * DIMC];           /* qkv_w -> half */
__device__ __align__(256) __half g_wph[DIMC * DIMC];            /* proj_w -> half */

/* ======================= helpers ======================= */
__device__ __forceinline__ void cp16(const __half* dst_smem, const __half* src_gmem) {
    uint32_t d = (uint32_t)__cvta_generic_to_shared(dst_smem);
    asm volatile("cp.async.cg.shared.global [%0], [%1], 16;" :: "r"(d), "l"(src_gmem) : "memory");
}
__device__ __forceinline__ void cp_commit() {
    asm volatile("cp.async.commit_group;" ::: "memory");
}
__device__ __forceinline__ void cp_wait0() {
    asm volatile("cp.async.wait_group 0;" ::: "memory");
}
/* m16n8k16 f16 mma, fp32 accumulate */
__device__ __forceinline__ void mma16(float* c, const uint32_t* a, uint32_t b0, uint32_t b1) {
    asm volatile(
        "mma.sync.aligned.m16n8k16.row.col.f32.f16.f16.f32 "
        "{%0,%1,%2,%3}, {%4,%5,%6,%7}, {%8,%9}, {%0,%1,%2,%3};"
        : "+f"(c[0]), "+f"(c[1]), "+f"(c[2]), "+f"(c[3])
        : "r"(a[0]), "r"(a[1]), "r"(a[2]), "r"(a[3]), "r"(b0), "r"(b1));
}
__device__ __forceinline__ void split_h(float v, __half& hi, __half& lo) {
    hi = __float2half_rn(v);
    lo = __float2half_rn(v - __half2float(hi));
}

/* ============================================================================
 * fp16 tensor-core GEMM: C[M x N] = A[M x 384] * W[N x 384]^T + bias[N]
 * A, W are half; C fp32. 128x128 CTA tile, 4 warps (2x2), 64x64 warp tile.
 * cp.async double-buffered; smem stride 40 halves (conflict-free frags).
 * ==========================================================================*/
template<int N, bool SCALE_Q>
__global__ void __launch_bounds__(128)
gemm_mma(const __half* __restrict__ A, const __half* __restrict__ W,
         const float* __restrict__ bias, float* __restrict__ C)
{
    extern __shared__ __align__(16) __half hsm[];
    const int tid  = threadIdx.x;
    const int m0   = blockIdx.y * 128;
    const int n0   = blockIdx.x * 128;
    const int wid  = tid >> 5, lane = tid & 31;
    const int wm   = wid >> 1, wn = wid & 1;
    const int grp  = lane >> 2, sub = lane & 3;

    float acc[4][8][4];
    #pragma unroll
    for (int mt = 0; mt < 4; mt++)
        #pragma unroll
        for (int nt = 0; nt < 8; nt++)
            #pragma unroll
            for (int r = 0; r < 4; r++) acc[mt][nt][r] = 0.f;

    auto prefetch = [&](int kc, int buf) {
        __half* As = hsm + buf * STAGE_HALFS;
        __half* Bs = As + 128 * SPADH;
        const int k0 = kc * BK;
        #pragma unroll
        for (int i = 0; i < 4; i++) {
            const int idx = tid + i * 128;          /* 0..511 */
            const int r = idx >> 2, q = idx & 3;    /* row, 8-half slot */
            cp16(As + r * SPADH + q * 8, A + (size_t)(m0 + r) * DIMC + k0 + q * 8);
            cp16(Bs + r * SPADH + q * 8, W + (size_t)(n0 + r) * DIMC + k0 + q * 8);
        }
        cp_commit();
    };

    prefetch(0, 0);

    for (int kc = 0; kc < NCHUNK; kc++) {
        cp_wait0();
        __syncthreads();
        if (kc + 1 < NCHUNK) prefetch(kc + 1, (kc + 1) & 1);

        const uint32_t* As = (const uint32_t*)(hsm + (kc & 1) * STAGE_HALFS);
        const uint32_t* Bs = As + 128 * SPADH / 2;

        #pragma unroll
        for (int ks = 0; ks < 2; ks++) {            /* two k16 steps per 32-half chunk */
            const int kkw = ks * 8;                 /* k offset in uint32 units */
            uint32_t a[4][4];
            #pragma unroll
            for (int mt = 0; mt < 4; mt++) {
                const uint32_t* p = As + (wm * 64 + mt * 16 + grp) * (SPADH / 2) + kkw + sub;
                a[mt][0] = p[0];
                a[mt][1] = p[8 * (SPADH / 2)];
                a[mt][2] = p[4];
                a[mt][3] = p[8 * (SPADH / 2) + 4];
            }
            #pragma unroll
            for (int nt = 0; nt < 8; nt++) {
                const uint32_t* p = Bs + (wn * 64 + nt * 8 + grp) * (SPADH / 2) + kkw + sub;
                const uint32_t b0 = p[0], b1 = p[4];
                #pragma unroll
                for (int mt = 0; mt < 4; mt++)
                    mma16(acc[mt][nt], a[mt], b0, b1);
            }
        }
        __syncthreads();
    }

    const bool do_scale = SCALE_Q && (n0 < DIMC);
    #pragma unroll
    for (int mt = 0; mt < 4; mt++) {
        const int r0 = m0 + wm * 64 + mt * 16 + grp;
        #pragma unroll
        for (int nt = 0; nt < 8; nt++) {
            const int col = n0 + wn * 64 + nt * 8 + 2 * sub;
            const float2 bv = *reinterpret_cast<const float2*>(&bias[col]);
            float2 o0 = make_float2(acc[mt][nt][0] + bv.x, acc[mt][nt][1] + bv.y);
            float2 o1 = make_float2(acc[mt][nt][2] + bv.x, acc[mt][nt][3] + bv.y);
            if (do_scale) {
                o0.x *= QK_SCALE; o0.y *= QK_SCALE;
                o1.x *= QK_SCALE; o1.y *= QK_SCALE;
            }
            *reinterpret_cast<float2*>(&C[(size_t)r0 * N + col])       = o0;
            *reinterpret_cast<float2*>(&C[(size_t)(r0 + 8) * N + col]) = o1;
        }
    }
}

/* ============================================================================ */
__global__ void cvt_f2h(const float4* __restrict__ src, __half2* __restrict__ dst, int n4)
{
    const int i = blockIdx.x * blockDim.x + threadIdx.x;
    if (i < n4) {
        const float4 v = src[i];
        dst[2 * i]     = __floats2half2_rn(v.x, v.y);
        dst[2 * i + 1] = __floats2half2_rn(v.z, v.w);
    }
}

__global__ void bias_gather(const float* __restrict__ bias_table,
                            const int* __restrict__ rel_index)
{
    const int h = blockIdx.x;
    for (int idx = threadIdx.x; idx < WIN_N * WIN_N; idx += blockDim.x)
        g_bias[h * WIN_N * WIN_N + idx] = bias_table[rel_index[idx] * NHEAD + h];
}

/* ============================================================================
 * Windowed attention via split-fp16 mma.sync (error-compensated, ~fp32 exact):
 *   X*Y ~= xh*yh + xh*yl + xl*yh   (residual ~2^-24)
 * One block (128 thr, 4 warps) per (head, window). Softmax in registers.
 * Rows padded 49->64; logit cols >=49 masked; P cols 56..63 zeroed (K pad 64).
 * ==========================================================================*/
__global__ void __launch_bounds__(128)
win_attn()
{
    extern __shared__ __align__(16) __half sm[];
    __half* qh  = sm + OFF_QH;  __half* ql  = sm + OFF_QL;
    __half* kh  = sm + OFF_KH;  __half* kl  = sm + OFF_KL;
    __half* vth = sm + OFF_VTH; __half* vtl = sm + OFF_VTL;
    __half* ph  = sm + OFF_PH;  __half* pl  = sm + OFF_PL;

    const int h = blockIdx.x;
    const int b = blockIdx.y;
    const int tid = threadIdx.x;
    const int wid = tid >> 5, lane = tid & 31;
    const int grp = lane >> 2, sub = lane & 3;

    /* ---- load q/k/v (rows padded to 64 with zeros), split hi/lo fp16 ---- */
    const float* base = g_qkv + (size_t)b * WIN_N * QKV_N + h * HD;
    #pragma unroll
    for (int i = 0; i < 16; i++) {
        const int idx = tid + i * 128;          /* 0..2047 */
        const int r = idx >> 5, d = idx & 31;
        float qv = 0.f, kv = 0.f, vv = 0.f;
        if (r < WIN_N) {
            const float* p = base + (size_t)r * QKV_N + d;
            qv = p[0]; kv = p[DIMC]; vv = p[2 * DIMC];
        }
        __half hi, lo;
        split_h(qv, hi, lo); qh[r * AQH + d] = hi; ql[r * AQH + d] = lo;
        split_h(kv, hi, lo); kh[r * AQH + d] = hi; kl[r * AQH + d] = lo;
        split_h(vv, hi, lo); vth[d * AVH + r] = hi; vtl[d * AVH + r] = lo;  /* transposed */
    }
    __syncthreads();

    /* ---- QK^T: warp w -> rows 16w..16w+15, cols 0..55 ---- */
    const int r0 = wid * 16;
    const int ra = r0 + grp, rb = ra + 8;
    float acc[7][4];
    #pragma unroll
    for (int nt = 0; nt < 7; nt++)
        #pragma unroll
        for (int r = 0; r < 4; r++) acc[nt][r] = 0.f;

    #pragma unroll
    for (int ks = 0; ks < 2; ks++) {            /* HD=32 -> two k16 steps */
        const int kkw = ks * 8;
        uint32_t ah[4], al[4];
        {
            const uint32_t* pH = (const uint32_t*)qh + ra * (AQH / 2) + kkw + sub;
            const uint32_t* pL = (const uint32_t*)ql + ra * (AQH / 2) + kkw + sub;
            ah[0] = pH[0]; ah[1] = pH[8 * (AQH / 2)]; ah[2] = pH[4]; ah[3] = pH[8 * (AQH / 2) + 4];
            al[0] = pL[0]; al[1] = pL[8 * (AQH / 2)]; al[2] = pL[4]; al[3] = pL[8 * (AQH / 2) + 4];
        }
        #pragma unroll
        for (int nt = 0; nt < 7; nt++) {
            const uint32_t* bH = (const uint32_t*)kh + (nt * 8 + grp) * (AQH / 2) + kkw + sub;
            const uint32_t* bL = (const uint32_t*)kl + (nt * 8 + grp) * (AQH / 2) + kkw + sub;
            const uint32_t bh0 = bH[0], bh1 = bH[4];
            const uint32_t bl0 = bL[0], bl1 = bL[4];
            mma16(acc[nt], ah, bh0, bh1);
            mma16(acc[nt], ah, bl0, bl1);
            mma16(acc[nt], al, bh0, bh1);
        }
    }

    /* ---- bias add + column mask ---- */
    const float* bsrc = g_bias + h * WIN_N * WIN_N;
    #pragma unroll
    for (int nt = 0; nt < 7; nt++) {
        const int c = 8 * nt + 2 * sub;
        if (c < WIN_N) {
            if (ra < WIN_N) acc[nt][0] += bsrc[ra * WIN_N + c];
            if (rb < WIN_N) acc[nt][2] += bsrc[rb * WIN_N + c];
        } else { acc[nt][0] = -1e30f; acc[nt][2] = -1e30f; }
        if (c + 1 < WIN_N) {
            if (ra < WIN_N) acc[nt][1] += bsrc[ra * WIN_N + c + 1];
            if (rb < WIN_N) acc[nt][3] += bsrc[rb * WIN_N + c + 1];
        } else { acc[nt][1] = -1e30f; acc[nt][3] = -1e30f; }
    }

    /* ---- softmax in registers ---- */
    float mx0 = -1e30f, mx1 = -1e30f;
    #pragma unroll
    for (int nt = 0; nt < 7; nt++) {
        mx0 = fmaxf(mx0, fmaxf(acc[nt][0], acc[nt][1]));
        mx1 = fmaxf(mx1, fmaxf(acc[nt][2], acc[nt][3]));
    }
    mx0 = fmaxf(mx0, __shfl_xor_sync(0xffffffffu, mx0, 1));
    mx0 = fmaxf(mx0, __shfl_xor_sync(0xffffffffu, mx0, 2));
    mx1 = fmaxf(mx1, __shfl_xor_sync(0xffffffffu, mx1, 1));
    mx1 = fmaxf(mx1, __shfl_xor_sync(0xffffffffu, mx1, 2));
    float s0 = 0.f, s1 = 0.f;
    #pragma unroll
    for (int nt = 0; nt < 7; nt++) {
        acc[nt][0] = __expf(acc[nt][0] - mx0);
        acc[nt][1] = __expf(acc[nt][1] - mx0);
        acc[nt][2] = __expf(acc[nt][2] - mx1);
        acc[nt][3] = __expf(acc[nt][3] - mx1);
        s0 += acc[nt][0] + acc[nt][1];
        s1 += acc[nt][2] + acc[nt][3];
    }
    s0 += __shfl_xor_sync(0xffffffffu, s0, 1);
    s0 += __shfl_xor_sync(0xffffffffu, s0, 2);
    s1 += __shfl_xor_sync(0xffffffffu, s1, 1);
    s1 += __shfl_xor_sync(0xffffffffu, s1, 2);
    const float i0 = 1.f / s0, i1 = 1.f / s1;

    /* ---- store P split (rows 16w..16w+15, cols 0..55) + zero cols 56..63 ---- */
    #pragma unroll
    for (int nt = 0; nt < 7; nt++) {
        const int c = 8 * nt + 2 * sub;
        const float p00 = acc[nt][0] * i0, p01 = acc[nt][1] * i0;
        const float p10 = acc[nt][2] * i1, p11 = acc[nt][3] * i1;
        __half hi, lo;
        split_h(p00, hi, lo); ph[ra * AVH + c]     = hi; pl[ra * AVH + c]     = lo;
        split_h(p01, hi, lo); ph[ra * AVH + c + 1] = hi; pl[ra * AVH + c + 1] = lo;
        split_h(p10, hi, lo); ph[rb * AVH + c]     = hi; pl[rb * AVH + c]     = lo;
        split_h(p11, hi, lo); ph[rb * AVH + c + 1] = hi; pl[rb * AVH + c + 1] = lo;
    }
    {   /* zero halves 56+2sub, 57+2sub of rows ra, rb (one uint32 each) */
        ((uint32_t*)ph)[ra * (AVH / 2) + 28 + sub] = 0u;
        ((uint32_t*)pl)[ra * (AVH / 2) + 28 + sub] = 0u;
        ((uint32_t*)ph)[rb * (AVH / 2) + 28 + sub] = 0u;
        ((uint32_t*)pl)[rb * (AVH / 2) + 28 + sub] = 0u;
    }
    __syncwarp();   /* each warp reads back only its own 16 P rows */

    /* ---- PV: out rows 16w..16w+15, d cols 0..31, K = 64 (4 k16 steps) ---- */
    float o[4][4];
    #pragma unroll
    for (int nt = 0; nt < 4; nt++)
        #pragma unroll
        for (int r = 0; r < 4; r++) o[nt][r] = 0.f;

    #pragma unroll
    for (int ks = 0; ks < 4; ks++) {
        const int kkw = ks * 8;
        uint32_t ah[4], al[4];
        {
            const uint32_t* pH = (const uint32_t*)ph + ra * (AVH / 2) + kkw + sub;
            const uint32_t* pL = (const uint32_t*)pl + ra * (AVH / 2) + kkw + sub;
            ah[0] = pH[0]; ah[1] = pH[8 * (AVH / 2)]; ah[2] = pH[4]; ah[3] = pH[8 * (AVH / 2) + 4];
            al[0] = pL[0]; al[1] = pL[8 * (AVH / 2)]; al[2] = pL[4]; al[3] = pL[8 * (AVH / 2) + 4];
        }
        #pragma unroll
        for (int nt = 0; nt < 4; nt++) {
            const uint32_t* bH = (const uint32_t*)vth + (nt * 8 + grp) * (AVH / 2) + kkw + sub;
            const uint32_t* bL = (const uint32_t*)vtl + (nt * 8 + grp) * (AVH / 2) + kkw + sub;
            const uint32_t bh0 = bH[0], bh1 = bH[4];
            const uint32_t bl0 = bL[0], bl1 = bL[4];
            mma16(o[nt], ah, bh0, bh1);
            mma16(o[nt], ah, bl0, bl1);
            mma16(o[nt], al, bh0, bh1);
        }
    }

    /* ---- store ctx as half (feeds proj GEMM directly) ---- */
    __half* ctx = g_ctx + (size_t)b * WIN_N * DIMC + h * HD;
    #pragma unroll
    for (int nt = 0; nt < 4; nt++) {
        const int d0 = 8 * nt + 2 * sub;
        if (ra < WIN_N)
            *reinterpret_cast<__half2*>(&ctx[(size_t)ra * DIMC + d0]) =
                __floats2half2_rn(o[nt][0], o[nt][1]);
        if (rb < WIN_N)
            *reinterpret_cast<__half2*>(&ctx[(size_t)rb * DIMC + d0]) =
                __floats2half2_rn(o[nt][2], o[nt][3]);
    }
}

/* ============================================================================ */
extern "C" void kernel_launch(void* const* d_in, const int* in_sizes, int n_in,
                              void* d_out, int out_size)
{
    const float* x          = (const float*)d_in[0];
    const float* qkv_w      = (const float*)d_in[1];
    const float* qkv_b      = (const float*)d_in[2];
    const float* proj_w     = (const float*)d_in[3];
    const float* proj_b     = (const float*)d_in[4];
    const float* bias_table = (const float*)d_in[5];
    const int*   rel_index  = (const int*)d_in[6];
    float*       out        = (float*)d_out;

    float *qkv_ptr;
    __half *ctx_ptr, *xh_ptr, *wqh_ptr, *wph_ptr;
    cudaGetSymbolAddress((void**)&qkv_ptr, g_qkv);
    cudaGetSymbolAddress((void**)&ctx_ptr, g_ctx);
    cudaGetSymbolAddress((void**)&xh_ptr,  g_xh);
    cudaGetSymbolAddress((void**)&wqh_ptr, g_wqh);
    cudaGetSymbolAddress((void**)&wph_ptr, g_wph);

    cudaFuncSetAttribute(gemm_mma<QKV_N, true>, cudaFuncAttributeMaxDynamicSharedMemorySize, SMEM_DYN);
    cudaFuncSetAttribute(gemm_mma<DIMC, false>, cudaFuncAttributeMaxDynamicSharedMemorySize, SMEM_DYN);
    cudaFuncSetAttribute(win_attn,              cudaFuncAttributeMaxDynamicSharedMemorySize, SMEM_ATT);

    /* 0) fp16 conversion of GEMM operands + bias gather */
    {
        const int nx = MROWS * DIMC / 4;
        cvt_f2h<<<(nx + 255) / 256, 256>>>((const float4*)x, (__half2*)xh_ptr, nx);
        const int nq = QKV_N * DIMC / 4;
        cvt_f2h<<<(nq + 255) / 256, 256>>>((const float4*)qkv_w, (__half2*)wqh_ptr, nq);
        const int np = DIMC * DIMC / 4;
        cvt_f2h<<<(np + 255) / 256, 256>>>((const float4*)proj_w, (__half2*)wph_ptr, np);
        bias_gather<<<NHEAD, 256>>>(bias_table, rel_index);
    }

    /* 1) QKV = X * Wqkv^T + b (q pre-scaled), fp16 mma.sync */
    dim3 g1(QKV_N / 128, MROWS / 128);   /* (9, 1568) */
    gemm_mma<QKV_N, true><<<g1, 128, SMEM_DYN>>>(xh_ptr, wqh_ptr, qkv_b, qkv_ptr);

    /* 2) windowed attention, split-fp16 mma.sync */
    dim3 g2(NHEAD, BWIN);                /* (12, 4096) */
    win_attn<<<g2, 128, SMEM_ATT>>>();

    /* 3) OUT = CTX * Wproj^T + b, fp16 mma.sync */
    dim3 g3(DIMC / 128, MROWS / 128);    /* (3, 1568) */
    gemm_mma<DIMC, false><<<g3, 128, SMEM_DYN>>>(ctx_ptr, wph_ptr, proj_b, out);
}

// round 15
// speedup vs baseline: 1.7731x; 1.0522x over previous
#include <cuda_runtime.h>
#include <cuda_fp16.h>
#include <cstdint>

#define WIN_N   49
#define DIMC    384
#define NHEAD   12
#define HD      32
#define BWIN    4096
#define MROWS   (BWIN * WIN_N)      /* 200704 */
#define QKV_N   (3 * DIMC)          /* 1152   */

#define QK_SCALE 0.17677669529663687f   /* 32^-0.5 */

/* ---- fp16 GEMM staging ---- */
#define BK      32                  /* K halves per pipeline chunk (64 B/row) */
#define NCHUNK  (DIMC / BK)         /* 12 */
#define SPADH   40                  /* smem row stride in halves: banks (20g+s) conflict-free */
#define STAGE_HALFS (2 * 128 * SPADH)          /* A + B tile per stage = 10240 halves */
#define SMEM_DYN (2 * STAGE_HALFS * 2)         /* 40960 B double buffered */

/* ---- attention smem (halves) ---- */
#define AQH     40                  /* q/k row stride (64 x 32) */
#define AVH     72                  /* vt (32 x 64) / P (64 x 64) row stride */
#define OFF_QH  0
#define OFF_QL  (OFF_QH + 64 * AQH)
#define OFF_KH  (OFF_QL + 64 * AQH)
#define OFF_KL  (OFF_KH + 64 * AQH)
#define OFF_VTH (OFF_KL + 64 * AQH)
#define OFF_PH  (OFF_VTH + 32 * AVH)
#define ATT_HALFS (OFF_PH + 64 * AVH)          /* 17152 halves */
#define SMEM_ATT (ATT_HALFS * 2)               /* 34304 B */

/* -------- scratch: static device globals -------- */
__device__ __align__(256) float  g_qkv[(size_t)MROWS * QKV_N];  /* fp32 q|k|v (q pre-scaled) */
__device__ __align__(256) __half g_ctx[(size_t)MROWS * DIMC];   /* attention out (half) */
__device__ __align__(256) float  g_bias[NHEAD * WIN_N * WIN_N]; /* gathered rel-pos bias */
__device__ __align__(256) __half g_wqh[QKV_N * DIMC];           /* qkv_w -> half */
__device__ __align__(256) __half g_wph[DIMC * DIMC];            /* proj_w -> half */

/* ======================= helpers ======================= */
__device__ __forceinline__ void cp16(const __half* dst_smem, const __half* src_gmem) {
    uint32_t d = (uint32_t)__cvta_generic_to_shared(dst_smem);
    asm volatile("cp.async.cg.shared.global [%0], [%1], 16;" :: "r"(d), "l"(src_gmem) : "memory");
}
__device__ __forceinline__ void cp_commit() {
    asm volatile("cp.async.commit_group;" ::: "memory");
}
__device__ __forceinline__ void cp_wait0() {
    asm volatile("cp.async.wait_group 0;" ::: "memory");
}
/* m16n8k16 f16 mma, fp32 accumulate */
__device__ __forceinline__ void mma16(float* c, const uint32_t* a, uint32_t b0, uint32_t b1) {
    asm volatile(
        "mma.sync.aligned.m16n8k16.row.col.f32.f16.f16.f32 "
        "{%0,%1,%2,%3}, {%4,%5,%6,%7}, {%8,%9}, {%0,%1,%2,%3};"
        : "+f"(c[0]), "+f"(c[1]), "+f"(c[2]), "+f"(c[3])
        : "r"(a[0]), "r"(a[1]), "r"(a[2]), "r"(a[3]), "r"(b0), "r"(b1));
}
__device__ __forceinline__ void split_h(float v, __half& hi, __half& lo) {
    hi = __float2half_rn(v);
    lo = __float2half_rn(v - __half2float(hi));
}

/* ============================================================================
 * fp16 tensor-core GEMM: C[M x N] = A[M x 384] * W[N x 384]^T + bias[N]
 * AF32: A is fp32 in gmem, converted to half in-register (fused cvt), staged
 *       via LDG->cvt->STS with register double buffering.
 * else: A is half, staged via cp.async (same group as W).
 * 128x128 CTA tile, 4 warps (2x2), 64x64 warp tile, double-buffered smem.
 * ==========================================================================*/
template<int N, bool SCALE_Q, bool AF32>
__global__ void __launch_bounds__(128)
gemm_mma(const void* __restrict__ Av, const __half* __restrict__ W,
         const float* __restrict__ bias, float* __restrict__ C)
{
    extern __shared__ __align__(16) __half hsm[];
    const float*  Af = (const float*)Av;
    const __half* Ah = (const __half*)Av;

    const int tid  = threadIdx.x;
    const int m0   = blockIdx.y * 128;
    const int n0   = blockIdx.x * 128;
    const int wid  = tid >> 5, lane = tid & 31;
    const int wm   = wid >> 1, wn = wid & 1;
    const int grp  = lane >> 2, sub = lane & 3;

    float acc[4][8][4];
    #pragma unroll
    for (int mt = 0; mt < 4; mt++)
        #pragma unroll
        for (int nt = 0; nt < 8; nt++)
            #pragma unroll
            for (int r = 0; r < 4; r++) acc[mt][nt][r] = 0.f;

    float4 areg[8];   /* AF32 staging: 4 slots x 8 floats */

    auto cpW = [&](int kc, int buf) {
        __half* Bs = hsm + buf * STAGE_HALFS + 128 * SPADH;
        const int k0 = kc * BK;
        #pragma unroll
        for (int i = 0; i < 4; i++) {
            const int idx = tid + i * 128;
            const int r = idx >> 2, q = idx & 3;
            cp16(Bs + r * SPADH + q * 8, W + (size_t)(n0 + r) * DIMC + k0 + q * 8);
        }
    };
    auto cpA = [&](int kc, int buf) {        /* !AF32 path */
        __half* As = hsm + buf * STAGE_HALFS;
        const int k0 = kc * BK;
        #pragma unroll
        for (int i = 0; i < 4; i++) {
            const int idx = tid + i * 128;
            const int r = idx >> 2, q = idx & 3;
            cp16(As + r * SPADH + q * 8, Ah + (size_t)(m0 + r) * DIMC + k0 + q * 8);
        }
    };
    auto ldgA = [&](int kc) {                /* AF32 path: gmem fp32 -> regs */
        const int k0 = kc * BK;
        #pragma unroll
        for (int i = 0; i < 4; i++) {
            const int idx = tid + i * 128;
            const int r = idx >> 2, q = idx & 3;
            const float4* p = reinterpret_cast<const float4*>(
                Af + (size_t)(m0 + r) * DIMC + k0 + q * 8);
            areg[2 * i]     = p[0];
            areg[2 * i + 1] = p[1];
        }
    };
    auto stsA = [&](int buf) {               /* regs -> half smem */
        __half* As = hsm + buf * STAGE_HALFS;
        #pragma unroll
        for (int i = 0; i < 4; i++) {
            const int idx = tid + i * 128;
            const int r = idx >> 2, q = idx & 3;
            const float4 v0 = areg[2 * i], v1 = areg[2 * i + 1];
            __half2 h0 = __floats2half2_rn(v0.x, v0.y);
            __half2 h1 = __floats2half2_rn(v0.z, v0.w);
            __half2 h2 = __floats2half2_rn(v1.x, v1.y);
            __half2 h3 = __floats2half2_rn(v1.z, v1.w);
            uint4 u;
            u.x = *(uint32_t*)&h0; u.y = *(uint32_t*)&h1;
            u.z = *(uint32_t*)&h2; u.w = *(uint32_t*)&h3;
            *reinterpret_cast<uint4*>(As + r * SPADH + q * 8) = u;
        }
    };

    /* prologue */
    if (AF32) { ldgA(0); cpW(0, 0); }
    else      { cpA(0, 0); cpW(0, 0); }
    cp_commit();

    for (int kc = 0; kc < NCHUNK; kc++) {
        cp_wait0();
        if (AF32) stsA(kc & 1);
        __syncthreads();
        if (kc + 1 < NCHUNK) {
            if (AF32) { ldgA(kc + 1); cpW(kc + 1, (kc + 1) & 1); }
            else      { cpA(kc + 1, (kc + 1) & 1); cpW(kc + 1, (kc + 1) & 1); }
            cp_commit();
        }

        const uint32_t* As = (const uint32_t*)(hsm + (kc & 1) * STAGE_HALFS);
        const uint32_t* Bs = As + 128 * SPADH / 2;

        #pragma unroll
        for (int ks = 0; ks < 2; ks++) {
            const int kkw = ks * 8;
            uint32_t a[4][4];
            #pragma unroll
            for (int mt = 0; mt < 4; mt++) {
                const uint32_t* p = As + (wm * 64 + mt * 16 + grp) * (SPADH / 2) + kkw + sub;
                a[mt][0] = p[0];
                a[mt][1] = p[8 * (SPADH / 2)];
                a[mt][2] = p[4];
                a[mt][3] = p[8 * (SPADH / 2) + 4];
            }
            #pragma unroll
            for (int nt = 0; nt < 8; nt++) {
                const uint32_t* p = Bs + (wn * 64 + nt * 8 + grp) * (SPADH / 2) + kkw + sub;
                const uint32_t b0 = p[0], b1 = p[4];
                #pragma unroll
                for (int mt = 0; mt < 4; mt++)
                    mma16(acc[mt][nt], a[mt], b0, b1);
            }
        }
        __syncthreads();
    }

    const bool do_scale = SCALE_Q && (n0 < DIMC);
    #pragma unroll
    for (int mt = 0; mt < 4; mt++) {
        const int r0 = m0 + wm * 64 + mt * 16 + grp;
        #pragma unroll
        for (int nt = 0; nt < 8; nt++) {
            const int col = n0 + wn * 64 + nt * 8 + 2 * sub;
            const float2 bv = *reinterpret_cast<const float2*>(&bias[col]);
            float2 o0 = make_float2(acc[mt][nt][0] + bv.x, acc[mt][nt][1] + bv.y);
            float2 o1 = make_float2(acc[mt][nt][2] + bv.x, acc[mt][nt][3] + bv.y);
            if (do_scale) {
                o0.x *= QK_SCALE; o0.y *= QK_SCALE;
                o1.x *= QK_SCALE; o1.y *= QK_SCALE;
            }
            *reinterpret_cast<float2*>(&C[(size_t)r0 * N + col])       = o0;
            *reinterpret_cast<float2*>(&C[(size_t)(r0 + 8) * N + col]) = o1;
        }
    }
}

/* ============================================================================ */
__global__ void cvt_f2h(const float4* __restrict__ src, __half2* __restrict__ dst, int n4)
{
    const int i = blockIdx.x * blockDim.x + threadIdx.x;
    if (i < n4) {
        const float4 v = src[i];
        dst[2 * i]     = __floats2half2_rn(v.x, v.y);
        dst[2 * i + 1] = __floats2half2_rn(v.z, v.w);
    }
}

__global__ void bias_gather(const float* __restrict__ bias_table,
                            const int* __restrict__ rel_index)
{
    const int h = blockIdx.x;
    for (int idx = threadIdx.x; idx < WIN_N * WIN_N; idx += blockDim.x)
        g_bias[h * WIN_N * WIN_N + idx] = bias_table[rel_index[idx] * NHEAD + h];
}

/* ============================================================================
 * Windowed attention, fp16 mma.sync.
 * QK^T error-compensated: qh*kh + qh*kl + ql*kh  (~fp32 accurate -> softmax).
 * PV single MMA: ph*vh (p in [0,1], v fp16; RMS rel err ~3.4e-4, in budget).
 * One block (128 thr, 4 warps) per (head, window). Softmax in registers.
 * NOTE: vth is written for ALL 64 sequence columns (zeros beyond 49) — the
 * PV MMA reads K=0..63 and 0 * uninitialized-NaN = NaN (R14 lesson).
 * ==========================================================================*/
__global__ void __launch_bounds__(128)
win_attn()
{
    extern __shared__ __align__(16) __half sm[];
    __half* qh  = sm + OFF_QH;  __half* ql  = sm + OFF_QL;
    __half* kh  = sm + OFF_KH;  __half* kl  = sm + OFF_KL;
    __half* vth = sm + OFF_VTH;
    __half* ph  = sm + OFF_PH;

    const int h = blockIdx.x;
    const int b = blockIdx.y;
    const int tid = threadIdx.x;
    const int wid = tid >> 5, lane = tid & 31;
    const int grp = lane >> 2, sub = lane & 3;

    /* ---- load q/k/v (rows padded to 64 with zeros) ---- */
    const float* base = g_qkv + (size_t)b * WIN_N * QKV_N + h * HD;
    #pragma unroll
    for (int i = 0; i < 16; i++) {
        const int idx = tid + i * 128;          /* 0..2047 */
        const int r = idx >> 5, d = idx & 31;
        float qv = 0.f, kv = 0.f, vv = 0.f;
        if (r < WIN_N) {
            const float* p = base + (size_t)r * QKV_N + d;
            qv = p[0]; kv = p[DIMC]; vv = p[2 * DIMC];
        }
        __half hi, lo;
        split_h(qv, hi, lo); qh[r * AQH + d] = hi; ql[r * AQH + d] = lo;
        split_h(kv, hi, lo); kh[r * AQH + d] = hi; kl[r * AQH + d] = lo;
        vth[d * AVH + r] = __float2half_rn(vv);   /* transposed; zero for r>=49 */
    }
    __syncthreads();

    /* ---- QK^T: warp w -> rows 16w..16w+15, cols 0..55 ---- */
    const int r0 = wid * 16;
    const int ra = r0 + grp, rb = ra + 8;
    float acc[7][4];
    #pragma unroll
    for (int nt = 0; nt < 7; nt++)
        #pragma unroll
        for (int r = 0; r < 4; r++) acc[nt][r] = 0.f;

    #pragma unroll
    for (int ks = 0; ks < 2; ks++) {            /* HD=32 -> two k16 steps */
        const int kkw = ks * 8;
        uint32_t ah[4], al[4];
        {
            const uint32_t* pH = (const uint32_t*)qh + ra * (AQH / 2) + kkw + sub;
            const uint32_t* pL = (const uint32_t*)ql + ra * (AQH / 2) + kkw + sub;
            ah[0] = pH[0]; ah[1] = pH[8 * (AQH / 2)]; ah[2] = pH[4]; ah[3] = pH[8 * (AQH / 2) + 4];
            al[0] = pL[0]; al[1] = pL[8 * (AQH / 2)]; al[2] = pL[4]; al[3] = pL[8 * (AQH / 2) + 4];
        }
        #pragma unroll
        for (int nt = 0; nt < 7; nt++) {
            const uint32_t* bH = (const uint32_t*)kh + (nt * 8 + grp) * (AQH / 2) + kkw + sub;
            const uint32_t* bL = (const uint32_t*)kl + (nt * 8 + grp) * (AQH / 2) + kkw + sub;
            const uint32_t bh0 = bH[0], bh1 = bH[4];
            const uint32_t bl0 = bL[0], bl1 = bL[4];
            mma16(acc[nt], ah, bh0, bh1);
            mma16(acc[nt], ah, bl0, bl1);
            mma16(acc[nt], al, bh0, bh1);
        }
    }

    /* ---- bias add + column mask ---- */
    const float* bsrc = g_bias + h * WIN_N * WIN_N;
    #pragma unroll
    for (int nt = 0; nt < 7; nt++) {
        const int c = 8 * nt + 2 * sub;
        if (c < WIN_N) {
            if (ra < WIN_N) acc[nt][0] += bsrc[ra * WIN_N + c];
            if (rb < WIN_N) acc[nt][2] += bsrc[rb * WIN_N + c];
        } else { acc[nt][0] = -1e30f; acc[nt][2] = -1e30f; }
        if (c + 1 < WIN_N) {
            if (ra < WIN_N) acc[nt][1] += bsrc[ra * WIN_N + c + 1];
            if (rb < WIN_N) acc[nt][3] += bsrc[rb * WIN_N + c + 1];
        } else { acc[nt][1] = -1e30f; acc[nt][3] = -1e30f; }
    }

    /* ---- softmax in registers ---- */
    float mx0 = -1e30f, mx1 = -1e30f;
    #pragma unroll
    for (int nt = 0; nt < 7; nt++) {
        mx0 = fmaxf(mx0, fmaxf(acc[nt][0], acc[nt][1]));
        mx1 = fmaxf(mx1, fmaxf(acc[nt][2], acc[nt][3]));
    }
    mx0 = fmaxf(mx0, __shfl_xor_sync(0xffffffffu, mx0, 1));
    mx0 = fmaxf(mx0, __shfl_xor_sync(0xffffffffu, mx0, 2));
    mx1 = fmaxf(mx1, __shfl_xor_sync(0xffffffffu, mx1, 1));
    mx1 = fmaxf(mx1, __shfl_xor_sync(0xffffffffu, mx1, 2));
    float s0 = 0.f, s1 = 0.f;
    #pragma unroll
    for (int nt = 0; nt < 7; nt++) {
        acc[nt][0] = __expf(acc[nt][0] - mx0);
        acc[nt][1] = __expf(acc[nt][1] - mx0);
        acc[nt][2] = __expf(acc[nt][2] - mx1);
        acc[nt][3] = __expf(acc[nt][3] - mx1);
        s0 += acc[nt][0] + acc[nt][1];
        s1 += acc[nt][2] + acc[nt][3];
    }
    s0 += __shfl_xor_sync(0xffffffffu, s0, 1);
    s0 += __shfl_xor_sync(0xffffffffu, s0, 2);
    s1 += __shfl_xor_sync(0xffffffffu, s1, 1);
    s1 += __shfl_xor_sync(0xffffffffu, s1, 2);
    const float i0 = 1.f / s0, i1 = 1.f / s1;

    /* ---- store P (rows 16w..16w+15, cols 0..55) + zero cols 56..63 ---- */
    #pragma unroll
    for (int nt = 0; nt < 7; nt++) {
        const int c = 8 * nt + 2 * sub;
        ph[ra * AVH + c]     = __float2half_rn(acc[nt][0] * i0);
        ph[ra * AVH + c + 1] = __float2half_rn(acc[nt][1] * i0);
        ph[rb * AVH + c]     = __float2half_rn(acc[nt][2] * i1);
        ph[rb * AVH + c + 1] = __float2half_rn(acc[nt][3] * i1);
    }
    ((uint32_t*)ph)[ra * (AVH / 2) + 28 + sub] = 0u;
    ((uint32_t*)ph)[rb * (AVH / 2) + 28 + sub] = 0u;
    __syncwarp();   /* each warp reads back only its own 16 P rows */

    /* ---- PV: out rows 16w..16w+15, d cols 0..31, K = 64 (4 k16 steps) ---- */
    float o[4][4];
    #pragma unroll
    for (int nt = 0; nt < 4; nt++)
        #pragma unroll
        for (int r = 0; r < 4; r++) o[nt][r] = 0.f;

    #pragma unroll
    for (int ks = 0; ks < 4; ks++) {
        const int kkw = ks * 8;
        uint32_t ah[4];
        {
            const uint32_t* pH = (const uint32_t*)ph + ra * (AVH / 2) + kkw + sub;
            ah[0] = pH[0]; ah[1] = pH[8 * (AVH / 2)]; ah[2] = pH[4]; ah[3] = pH[8 * (AVH / 2) + 4];
        }
        #pragma unroll
        for (int nt = 0; nt < 4; nt++) {
            const uint32_t* bH = (const uint32_t*)vth + (nt * 8 + grp) * (AVH / 2) + kkw + sub;
            mma16(o[nt], ah, bH[0], bH[4]);
        }
    }

    /* ---- store ctx as half (feeds proj GEMM directly) ---- */
    __half* ctx = g_ctx + (size_t)b * WIN_N * DIMC + h * HD;
    #pragma unroll
    for (int nt = 0; nt < 4; nt++) {
        const int d0 = 8 * nt + 2 * sub;
        if (ra < WIN_N)
            *reinterpret_cast<__half2*>(&ctx[(size_t)ra * DIMC + d0]) =
                __floats2half2_rn(o[nt][0], o[nt][1]);
        if (rb < WIN_N)
            *reinterpret_cast<__half2*>(&ctx[(size_t)rb * DIMC + d0]) =
                __floats2half2_rn(o[nt][2], o[nt][3]);
    }
}

/* ============================================================================ */
extern "C" void kernel_launch(void* const* d_in, const int* in_sizes, int n_in,
                              void* d_out, int out_size)
{
    const float* x          = (const float*)d_in[0];
    const float* qkv_w      = (const float*)d_in[1];
    const float* qkv_b      = (const float*)d_in[2];
    const float* proj_w     = (const float*)d_in[3];
    const float* proj_b     = (const float*)d_in[4];
    const float* bias_table = (const float*)d_in[5];
    const int*   rel_index  = (const int*)d_in[6];
    float*       out        = (float*)d_out;

    float *qkv_ptr;
    __half *ctx_ptr, *wqh_ptr, *wph_ptr;
    cudaGetSymbolAddress((void**)&qkv_ptr, g_qkv);
    cudaGetSymbolAddress((void**)&ctx_ptr, g_ctx);
    cudaGetSymbolAddress((void**)&wqh_ptr, g_wqh);
    cudaGetSymbolAddress((void**)&wph_ptr, g_wph);

    cudaFuncSetAttribute(gemm_mma<QKV_N, true,  true>,  cudaFuncAttributeMaxDynamicSharedMemorySize, SMEM_DYN);
    cudaFuncSetAttribute(gemm_mma<DIMC,  false, false>, cudaFuncAttributeMaxDynamicSharedMemorySize, SMEM_DYN);
    cudaFuncSetAttribute(win_attn,                      cudaFuncAttributeMaxDynamicSharedMemorySize, SMEM_ATT);

    /* 0) weight fp16 conversion + bias gather (tiny; x cvt fused into GEMM) */
    {
        const int nq = QKV_N * DIMC / 4;
        cvt_f2h<<<(nq + 255) / 256, 256>>>((const float4*)qkv_w, (__half2*)wqh_ptr, nq);
        const int np = DIMC * DIMC / 4;
        cvt_f2h<<<(np + 255) / 256, 256>>>((const float4*)proj_w, (__half2*)wph_ptr, np);
        bias_gather<<<NHEAD, 256>>>(bias_table, rel_index);
    }

    /* 1) QKV = X * Wqkv^T + b (q pre-scaled), fp16 mma.sync, fused x->half */
    dim3 g1(QKV_N / 128, MROWS / 128);   /* (9, 1568) */
    gemm_mma<QKV_N, true, true><<<g1, 128, SMEM_DYN>>>(x, wqh_ptr, qkv_b, qkv_ptr);

    /* 2) windowed attention */
    dim3 g2(NHEAD, BWIN);                /* (12, 4096) */
    win_attn<<<g2, 128, SMEM_ATT>>>();

    /* 3) OUT = CTX * Wproj^T + b, fp16 mma.sync */
    dim3 g3(DIMC / 128, MROWS / 128);    /* (3, 1568) */
    gemm_mma<DIMC, false, false><<<g3, 128, SMEM_DYN>>>(ctx_ptr, wph_ptr, proj_b, out);
}

// round 16
// speedup vs baseline: 1.7793x; 1.0035x over previous
#include <cuda_runtime.h>
#include <cuda_fp16.h>
#include <cstdint>

#define WIN_N   49
#define DIMC    384
#define NHEAD   12
#define HD      32
#define BWIN    4096
#define MROWS   (BWIN * WIN_N)      /* 200704 */
#define QKV_N   (3 * DIMC)          /* 1152   */

#define QK_SCALE 0.17677669529663687f   /* 32^-0.5 */

/* ---- fp16 GEMM staging ---- */
#define BK      32                  /* K halves per pipeline chunk (64 B/row) */
#define NCHUNK  (DIMC / BK)         /* 12 */
#define SPADH   40                  /* smem row stride in halves: banks (20g+s) conflict-free */
#define STAGE_HALFS (2 * 128 * SPADH)          /* A + B tile per stage = 10240 halves */
#define SMEM_DYN (2 * STAGE_HALFS * 2)         /* 40960 B double buffered */

/* ---- attention smem (halves) ---- */
#define AQH     40                  /* q/k row stride (64 x 32) */
#define AVH     72                  /* vt (32 x 64) / P (64 x 64) row stride */
#define OFF_QH  0
#define OFF_QL  (OFF_QH + 64 * AQH)
#define OFF_KH  (OFF_QL + 64 * AQH)
#define OFF_KL  (OFF_KH + 64 * AQH)
#define OFF_VTH (OFF_KL + 64 * AQH)
#define OFF_PH  (OFF_VTH + 32 * AVH)
#define ATT_HALFS (OFF_PH + 64 * AVH)          /* 17152 halves */
#define SMEM_ATT (ATT_HALFS * 2)               /* 34304 B */

/* -------- scratch: static device globals -------- */
__device__ __align__(256) float  g_qkv[(size_t)MROWS * QKV_N];  /* fp32 q|k|v (q pre-scaled) */
__device__ __align__(256) __half g_ctx[(size_t)MROWS * DIMC];   /* attention out (half) */
__device__ __align__(256) float  g_bias[NHEAD * WIN_N * WIN_N]; /* gathered rel-pos bias */
__device__ __align__(256) __half g_wqh[QKV_N * DIMC];           /* qkv_w -> half */
__device__ __align__(256) __half g_wph[DIMC * DIMC];            /* proj_w -> half */

/* ======================= helpers ======================= */
__device__ __forceinline__ void cp16(const __half* dst_smem, const __half* src_gmem) {
    uint32_t d = (uint32_t)__cvta_generic_to_shared(dst_smem);
    asm volatile("cp.async.cg.shared.global [%0], [%1], 16;" :: "r"(d), "l"(src_gmem) : "memory");
}
__device__ __forceinline__ void cp_commit() {
    asm volatile("cp.async.commit_group;" ::: "memory");
}
__device__ __forceinline__ void cp_wait0() {
    asm volatile("cp.async.wait_group 0;" ::: "memory");
}
/* m16n8k16 f16 mma, fp32 accumulate */
__device__ __forceinline__ void mma16(float* c, const uint32_t* a, uint32_t b0, uint32_t b1) {
    asm volatile(
        "mma.sync.aligned.m16n8k16.row.col.f32.f16.f16.f32 "
        "{%0,%1,%2,%3}, {%4,%5,%6,%7}, {%8,%9}, {%0,%1,%2,%3};"
        : "+f"(c[0]), "+f"(c[1]), "+f"(c[2]), "+f"(c[3])
        : "r"(a[0]), "r"(a[1]), "r"(a[2]), "r"(a[3]), "r"(b0), "r"(b1));
}
__device__ __forceinline__ void split_h(float v, __half& hi, __half& lo) {
    hi = __float2half_rn(v);
    lo = __float2half_rn(v - __half2float(hi));
}

/* ============================================================================
 * fp16 tensor-core GEMM: C[M x N] = A[M x 384] * W[N x 384]^T + bias[N]
 * 256 threads, 8 warps in a 2x4 grid, 64x32 warp tile (acc = 64 regs/thread)
 * -> 2 CTAs/SM = 16 warps = 4 warps/SMSP for MMA latency hiding.
 * AF32: A fp32 in gmem, fused convert via LDG->cvt->STS (register staged).
 * else: A half via cp.async. Double-buffered smem, stride 40 halves.
 * ==========================================================================*/
template<int N, bool SCALE_Q, bool AF32>
__global__ void __launch_bounds__(256, 2)
gemm_mma(const void* __restrict__ Av, const __half* __restrict__ W,
         const float* __restrict__ bias, float* __restrict__ C)
{
    extern __shared__ __align__(16) __half hsm[];
    const float*  Af = (const float*)Av;
    const __half* Ah = (const __half*)Av;

    const int tid  = threadIdx.x;
    const int m0   = blockIdx.y * 128;
    const int n0   = blockIdx.x * 128;
    const int wid  = tid >> 5, lane = tid & 31;
    const int wm   = wid >> 2, wn = wid & 3;        /* 2 x 4 warp grid */
    const int grp  = lane >> 2, sub = lane & 3;

    float acc[4][4][4];                             /* 64 x 32 warp tile */
    #pragma unroll
    for (int mt = 0; mt < 4; mt++)
        #pragma unroll
        for (int nt = 0; nt < 4; nt++)
            #pragma unroll
            for (int r = 0; r < 4; r++) acc[mt][nt][r] = 0.f;

    float4 areg[4];   /* AF32 staging: 16 floats / thread */

    auto cpW = [&](int kc, int buf) {
        __half* Bs = hsm + buf * STAGE_HALFS + 128 * SPADH;
        const int k0 = kc * BK;
        #pragma unroll
        for (int i = 0; i < 2; i++) {
            const int idx = tid + i * 256;          /* 0..511 */
            const int r = idx >> 2, q = idx & 3;
            cp16(Bs + r * SPADH + q * 8, W + (size_t)(n0 + r) * DIMC + k0 + q * 8);
        }
    };
    auto cpA = [&](int kc, int buf) {        /* !AF32 path */
        __half* As = hsm + buf * STAGE_HALFS;
        const int k0 = kc * BK;
        #pragma unroll
        for (int i = 0; i < 2; i++) {
            const int idx = tid + i * 256;
            const int r = idx >> 2, q = idx & 3;
            cp16(As + r * SPADH + q * 8, Ah + (size_t)(m0 + r) * DIMC + k0 + q * 8);
        }
    };
    auto ldgA = [&](int kc) {                /* AF32: gmem fp32 -> regs */
        const int k0 = kc * BK;
        #pragma unroll
        for (int i = 0; i < 4; i++) {
            const int idx = tid + i * 256;          /* 0..1023 */
            const int r = idx >> 3, q = idx & 7;    /* row, float4-slot */
            areg[i] = *reinterpret_cast<const float4*>(
                Af + (size_t)(m0 + r) * DIMC + k0 + q * 4);
        }
    };
    auto stsA = [&](int buf) {               /* regs -> half smem */
        __half* As = hsm + buf * STAGE_HALFS;
        #pragma unroll
        for (int i = 0; i < 4; i++) {
            const int idx = tid + i * 256;
            const int r = idx >> 3, q = idx & 7;
            const float4 v = areg[i];
            __half2 h0 = __floats2half2_rn(v.x, v.y);
            __half2 h1 = __floats2half2_rn(v.z, v.w);
            uint2 u;
            u.x = *(uint32_t*)&h0; u.y = *(uint32_t*)&h1;
            *reinterpret_cast<uint2*>(As + r * SPADH + q * 4) = u;
        }
    };

    /* prologue */
    if (AF32) { ldgA(0); cpW(0, 0); }
    else      { cpA(0, 0); cpW(0, 0); }
    cp_commit();

    for (int kc = 0; kc < NCHUNK; kc++) {
        cp_wait0();
        if (AF32) stsA(kc & 1);
        __syncthreads();
        if (kc + 1 < NCHUNK) {
            if (AF32) { ldgA(kc + 1); cpW(kc + 1, (kc + 1) & 1); }
            else      { cpA(kc + 1, (kc + 1) & 1); cpW(kc + 1, (kc + 1) & 1); }
            cp_commit();
        }

        const uint32_t* As = (const uint32_t*)(hsm + (kc & 1) * STAGE_HALFS);
        const uint32_t* Bs = As + 128 * SPADH / 2;

        #pragma unroll
        for (int ks = 0; ks < 2; ks++) {
            const int kkw = ks * 8;
            uint32_t a[4][4];
            #pragma unroll
            for (int mt = 0; mt < 4; mt++) {
                const uint32_t* p = As + (wm * 64 + mt * 16 + grp) * (SPADH / 2) + kkw + sub;
                a[mt][0] = p[0];
                a[mt][1] = p[8 * (SPADH / 2)];
                a[mt][2] = p[4];
                a[mt][3] = p[8 * (SPADH / 2) + 4];
            }
            #pragma unroll
            for (int nt = 0; nt < 4; nt++) {
                const uint32_t* p = Bs + (wn * 32 + nt * 8 + grp) * (SPADH / 2) + kkw + sub;
                const uint32_t b0 = p[0], b1 = p[4];
                #pragma unroll
                for (int mt = 0; mt < 4; mt++)
                    mma16(acc[mt][nt], a[mt], b0, b1);
            }
        }
        __syncthreads();
    }

    const bool do_scale = SCALE_Q && (n0 < DIMC);
    #pragma unroll
    for (int mt = 0; mt < 4; mt++) {
        const int r0 = m0 + wm * 64 + mt * 16 + grp;
        #pragma unroll
        for (int nt = 0; nt < 4; nt++) {
            const int col = n0 + wn * 32 + nt * 8 + 2 * sub;
            const float2 bv = *reinterpret_cast<const float2*>(&bias[col]);
            float2 o0 = make_float2(acc[mt][nt][0] + bv.x, acc[mt][nt][1] + bv.y);
            float2 o1 = make_float2(acc[mt][nt][2] + bv.x, acc[mt][nt][3] + bv.y);
            if (do_scale) {
                o0.x *= QK_SCALE; o0.y *= QK_SCALE;
                o1.x *= QK_SCALE; o1.y *= QK_SCALE;
            }
            *reinterpret_cast<float2*>(&C[(size_t)r0 * N + col])       = o0;
            *reinterpret_cast<float2*>(&C[(size_t)(r0 + 8) * N + col]) = o1;
        }
    }
}

/* ============================================================================ */
__global__ void cvt_f2h(const float4* __restrict__ src, __half2* __restrict__ dst, int n4)
{
    const int i = blockIdx.x * blockDim.x + threadIdx.x;
    if (i < n4) {
        const float4 v = src[i];
        dst[2 * i]     = __floats2half2_rn(v.x, v.y);
        dst[2 * i + 1] = __floats2half2_rn(v.z, v.w);
    }
}

__global__ void bias_gather(const float* __restrict__ bias_table,
                            const int* __restrict__ rel_index)
{
    const int h = blockIdx.x;
    for (int idx = threadIdx.x; idx < WIN_N * WIN_N; idx += blockDim.x)
        g_bias[h * WIN_N * WIN_N + idx] = bias_table[rel_index[idx] * NHEAD + h];
}

/* ============================================================================
 * Windowed attention, fp16 mma.sync.  [unchanged from R15 passing version]
 * QK^T error-compensated: qh*kh + qh*kl + ql*kh.  PV single MMA: ph*vh.
 * vth written for ALL 64 seq columns (zeros beyond 49) — R14 NaN lesson.
 * ==========================================================================*/
__global__ void __launch_bounds__(128)
win_attn()
{
    extern __shared__ __align__(16) __half sm[];
    __half* qh  = sm + OFF_QH;  __half* ql  = sm + OFF_QL;
    __half* kh  = sm + OFF_KH;  __half* kl  = sm + OFF_KL;
    __half* vth = sm + OFF_VTH;
    __half* ph  = sm + OFF_PH;

    const int h = blockIdx.x;
    const int b = blockIdx.y;
    const int tid = threadIdx.x;
    const int wid = tid >> 5, lane = tid & 31;
    const int grp = lane >> 2, sub = lane & 3;

    const float* base = g_qkv + (size_t)b * WIN_N * QKV_N + h * HD;
    #pragma unroll
    for (int i = 0; i < 16; i++) {
        const int idx = tid + i * 128;
        const int r = idx >> 5, d = idx & 31;
        float qv = 0.f, kv = 0.f, vv = 0.f;
        if (r < WIN_N) {
            const float* p = base + (size_t)r * QKV_N + d;
            qv = p[0]; kv = p[DIMC]; vv = p[2 * DIMC];
        }
        __half hi, lo;
        split_h(qv, hi, lo); qh[r * AQH + d] = hi; ql[r * AQH + d] = lo;
        split_h(kv, hi, lo); kh[r * AQH + d] = hi; kl[r * AQH + d] = lo;
        vth[d * AVH + r] = __float2half_rn(vv);   /* transposed; zero for r>=49 */
    }
    __syncthreads();

    const int r0 = wid * 16;
    const int ra = r0 + grp, rb = ra + 8;
    float acc[7][4];
    #pragma unroll
    for (int nt = 0; nt < 7; nt++)
        #pragma unroll
        for (int r = 0; r < 4; r++) acc[nt][r] = 0.f;

    #pragma unroll
    for (int ks = 0; ks < 2; ks++) {
        const int kkw = ks * 8;
        uint32_t ah[4], al[4];
        {
            const uint32_t* pH = (const uint32_t*)qh + ra * (AQH / 2) + kkw + sub;
            const uint32_t* pL = (const uint32_t*)ql + ra * (AQH / 2) + kkw + sub;
            ah[0] = pH[0]; ah[1] = pH[8 * (AQH / 2)]; ah[2] = pH[4]; ah[3] = pH[8 * (AQH / 2) + 4];
            al[0] = pL[0]; al[1] = pL[8 * (AQH / 2)]; al[2] = pL[4]; al[3] = pL[8 * (AQH / 2) + 4];
        }
        #pragma unroll
        for (int nt = 0; nt < 7; nt++) {
            const uint32_t* bH = (const uint32_t*)kh + (nt * 8 + grp) * (AQH / 2) + kkw + sub;
            const uint32_t* bL = (const uint32_t*)kl + (nt * 8 + grp) * (AQH / 2) + kkw + sub;
            const uint32_t bh0 = bH[0], bh1 = bH[4];
            const uint32_t bl0 = bL[0], bl1 = bL[4];
            mma16(acc[nt], ah, bh0, bh1);
            mma16(acc[nt], ah, bl0, bl1);
            mma16(acc[nt], al, bh0, bh1);
        }
    }

    const float* bsrc = g_bias + h * WIN_N * WIN_N;
    #pragma unroll
    for (int nt = 0; nt < 7; nt++) {
        const int c = 8 * nt + 2 * sub;
        if (c < WIN_N) {
            if (ra < WIN_N) acc[nt][0] += bsrc[ra * WIN_N + c];
            if (rb < WIN_N) acc[nt][2] += bsrc[rb * WIN_N + c];
        } else { acc[nt][0] = -1e30f; acc[nt][2] = -1e30f; }
        if (c + 1 < WIN_N) {
            if (ra < WIN_N) acc[nt][1] += bsrc[ra * WIN_N + c + 1];
            if (rb < WIN_N) acc[nt][3] += bsrc[rb * WIN_N + c + 1];
        } else { acc[nt][1] = -1e30f; acc[nt][3] = -1e30f; }
    }

    float mx0 = -1e30f, mx1 = -1e30f;
    #pragma unroll
    for (int nt = 0; nt < 7; nt++) {
        mx0 = fmaxf(mx0, fmaxf(acc[nt][0], acc[nt][1]));
        mx1 = fmaxf(mx1, fmaxf(acc[nt][2], acc[nt][3]));
    }
    mx0 = fmaxf(mx0, __shfl_xor_sync(0xffffffffu, mx0, 1));
    mx0 = fmaxf(mx0, __shfl_xor_sync(0xffffffffu, mx0, 2));
    mx1 = fmaxf(mx1, __shfl_xor_sync(0xffffffffu, mx1, 1));
    mx1 = fmaxf(mx1, __shfl_xor_sync(0xffffffffu, mx1, 2));
    float s0 = 0.f, s1 = 0.f;
    #pragma unroll
    for (int nt = 0; nt < 7; nt++) {
        acc[nt][0] = __expf(acc[nt][0] - mx0);
        acc[nt][1] = __expf(acc[nt][1] - mx0);
        acc[nt][2] = __expf(acc[nt][2] - mx1);
        acc[nt][3] = __expf(acc[nt][3] - mx1);
        s0 += acc[nt][0] + acc[nt][1];
        s1 += acc[nt][2] + acc[nt][3];
    }
    s0 += __shfl_xor_sync(0xffffffffu, s0, 1);
    s0 += __shfl_xor_sync(0xffffffffu, s0, 2);
    s1 += __shfl_xor_sync(0xffffffffu, s1, 1);
    s1 += __shfl_xor_sync(0xffffffffu, s1, 2);
    const float i0 = 1.f / s0, i1 = 1.f / s1;

    #pragma unroll
    for (int nt = 0; nt < 7; nt++) {
        const int c = 8 * nt + 2 * sub;
        ph[ra * AVH + c]     = __float2half_rn(acc[nt][0] * i0);
        ph[ra * AVH + c + 1] = __float2half_rn(acc[nt][1] * i0);
        ph[rb * AVH + c]     = __float2half_rn(acc[nt][2] * i1);
        ph[rb * AVH + c + 1] = __float2half_rn(acc[nt][3] * i1);
    }
    ((uint32_t*)ph)[ra * (AVH / 2) + 28 + sub] = 0u;
    ((uint32_t*)ph)[rb * (AVH / 2) + 28 + sub] = 0u;
    __syncwarp();

    float o[4][4];
    #pragma unroll
    for (int nt = 0; nt < 4; nt++)
        #pragma unroll
        for (int r = 0; r < 4; r++) o[nt][r] = 0.f;

    #pragma unroll
    for (int ks = 0; ks < 4; ks++) {
        const int kkw = ks * 8;
        uint32_t ah[4];
        {
            const uint32_t* pH = (const uint32_t*)ph + ra * (AVH / 2) + kkw + sub;
            ah[0] = pH[0]; ah[1] = pH[8 * (AVH / 2)]; ah[2] = pH[4]; ah[3] = pH[8 * (AVH / 2) + 4];
        }
        #pragma unroll
        for (int nt = 0; nt < 4; nt++) {
            const uint32_t* bH = (const uint32_t*)vth + (nt * 8 + grp) * (AVH / 2) + kkw + sub;
            mma16(o[nt], ah, bH[0], bH[4]);
        }
    }

    __half* ctx = g_ctx + (size_t)b * WIN_N * DIMC + h * HD;
    #pragma unroll
    for (int nt = 0; nt < 4; nt++) {
        const int d0 = 8 * nt + 2 * sub;
        if (ra < WIN_N)
            *reinterpret_cast<__half2*>(&ctx[(size_t)ra * DIMC + d0]) =
                __floats2half2_rn(o[nt][0], o[nt][1]);
        if (rb < WIN_N)
            *reinterpret_cast<__half2*>(&ctx[(size_t)rb * DIMC + d0]) =
                __floats2half2_rn(o[nt][2], o[nt][3]);
    }
}

/* ============================================================================ */
extern "C" void kernel_launch(void* const* d_in, const int* in_sizes, int n_in,
                              void* d_out, int out_size)
{
    const float* x          = (const float*)d_in[0];
    const float* qkv_w      = (const float*)d_in[1];
    const float* qkv_b      = (const float*)d_in[2];
    const float* proj_w     = (const float*)d_in[3];
    const float* proj_b     = (const float*)d_in[4];
    const float* bias_table = (const float*)d_in[5];
    const int*   rel_index  = (const int*)d_in[6];
    float*       out        = (float*)d_out;

    float *qkv_ptr;
    __half *ctx_ptr, *wqh_ptr, *wph_ptr;
    cudaGetSymbolAddress((void**)&qkv_ptr, g_qkv);
    cudaGetSymbolAddress((void**)&ctx_ptr, g_ctx);
    cudaGetSymbolAddress((void**)&wqh_ptr, g_wqh);
    cudaGetSymbolAddress((void**)&wph_ptr, g_wph);

    cudaFuncSetAttribute(gemm_mma<QKV_N, true,  true>,  cudaFuncAttributeMaxDynamicSharedMemorySize, SMEM_DYN);
    cudaFuncSetAttribute(gemm_mma<DIMC,  false, false>, cudaFuncAttributeMaxDynamicSharedMemorySize, SMEM_DYN);
    cudaFuncSetAttribute(win_attn,                      cudaFuncAttributeMaxDynamicSharedMemorySize, SMEM_ATT);

    /* 0) weight fp16 conversion + bias gather (tiny; x cvt fused into GEMM) */
    {
        const int nq = QKV_N * DIMC / 4;
        cvt_f2h<<<(nq + 255) / 256, 256>>>((const float4*)qkv_w, (__half2*)wqh_ptr, nq);
        const int np = DIMC * DIMC / 4;
        cvt_f2h<<<(np + 255) / 256, 256>>>((const float4*)proj_w, (__half2*)wph_ptr, np);
        bias_gather<<<NHEAD, 256>>>(bias_table, rel_index);
    }

    /* 1) QKV = X * Wqkv^T + b (q pre-scaled), fp16 mma.sync, fused x->half */
    dim3 g1(QKV_N / 128, MROWS / 128);   /* (9, 1568) */
    gemm_mma<QKV_N, true, true><<<g1, 256, SMEM_DYN>>>(x, wqh_ptr, qkv_b, qkv_ptr);

    /* 2) windowed attention */
    dim3 g2(NHEAD, BWIN);                /* (12, 4096) */
    win_attn<<<g2, 128, SMEM_ATT>>>();

    /* 3) OUT = CTX * Wproj^T + b, fp16 mma.sync */
    dim3 g3(DIMC / 128, MROWS / 128);    /* (3, 1568) */
    gemm_mma<DIMC, false, false><<<g3, 256, SMEM_DYN>>>(ctx_ptr, wph_ptr, proj_b, out);
}

// round 17
// speedup vs baseline: 1.8303x; 1.0287x over previous
#include <cuda_runtime.h>
#include <cuda_fp16.h>
#include <cstdint>

#define WIN_N   49
#define DIMC    384
#define NHEAD   12
#define HD      32
#define BWIN    4096
#define MROWS   (BWIN * WIN_N)      /* 200704 */
#define QKV_N   (3 * DIMC)          /* 1152   */

#define QK_SCALE 0.17677669529663687f   /* 32^-0.5 */

/* ---- fp16 GEMM staging ---- */
#define BK      32                  /* K halves per pipeline chunk (64 B/row) */
#define NCHUNK  (DIMC / BK)         /* 12 */
#define SPADH   40                  /* smem row stride in halves: banks (20g+s) conflict-free */
#define STAGE_HALFS (2 * 128 * SPADH)          /* A + B tile per stage = 10240 halves */
#define SMEM_DYN (2 * STAGE_HALFS * 2)         /* 40960 B double buffered */

/* ---- attention smem (halves): q, k, v^T, P ---- */
#define AQH     40                  /* q/k row stride (64 x 32) */
#define AVH     72                  /* vt (32 x 64) / P (64 x 64) row stride */
#define OFF_QH  0
#define OFF_KH  (OFF_QH + 64 * AQH)
#define OFF_VTH (OFF_KH + 64 * AQH)
#define OFF_PH  (OFF_VTH + 32 * AVH)
#define ATT_HALFS (OFF_PH + 64 * AVH)          /* 12032 halves */
#define SMEM_ATT (ATT_HALFS * 2)               /* 24064 B */

/* -------- scratch: static device globals -------- */
__device__ __align__(256) float  g_qkv[(size_t)MROWS * QKV_N];  /* fp32 q|k|v (q pre-scaled) */
__device__ __align__(256) __half g_ctx[(size_t)MROWS * DIMC];   /* attention out (half) */
__device__ __align__(256) float  g_bias[NHEAD * WIN_N * WIN_N]; /* gathered rel-pos bias */
__device__ __align__(256) __half g_wqh[QKV_N * DIMC];           /* qkv_w -> half */
__device__ __align__(256) __half g_wph[DIMC * DIMC];            /* proj_w -> half */

/* ======================= helpers ======================= */
__device__ __forceinline__ void cp16(const __half* dst_smem, const __half* src_gmem) {
    uint32_t d = (uint32_t)__cvta_generic_to_shared(dst_smem);
    asm volatile("cp.async.cg.shared.global [%0], [%1], 16;" :: "r"(d), "l"(src_gmem) : "memory");
}
__device__ __forceinline__ void cp_commit() {
    asm volatile("cp.async.commit_group;" ::: "memory");
}
__device__ __forceinline__ void cp_wait0() {
    asm volatile("cp.async.wait_group 0;" ::: "memory");
}
/* m16n8k16 f16 mma, fp32 accumulate */
__device__ __forceinline__ void mma16(float* c, const uint32_t* a, uint32_t b0, uint32_t b1) {
    asm volatile(
        "mma.sync.aligned.m16n8k16.row.col.f32.f16.f16.f32 "
        "{%0,%1,%2,%3}, {%4,%5,%6,%7}, {%8,%9}, {%0,%1,%2,%3};"
        : "+f"(c[0]), "+f"(c[1]), "+f"(c[2]), "+f"(c[3])
        : "r"(a[0]), "r"(a[1]), "r"(a[2]), "r"(a[3]), "r"(b0), "r"(b1));
}

/* ============================================================================
 * fp16 tensor-core GEMM: C[M x N] = A[M x 384] * W[N x 384]^T + bias[N]
 * 256 threads, 8 warps (2x4), 64x32 warp tile. [unchanged from R16 — at the
 * legacy-HMMA issue ceiling per R15/R16 profiles]
 * ==========================================================================*/
template<int N, bool SCALE_Q, bool AF32>
__global__ void __launch_bounds__(256, 2)
gemm_mma(const void* __restrict__ Av, const __half* __restrict__ W,
         const float* __restrict__ bias, float* __restrict__ C)
{
    extern __shared__ __align__(16) __half hsm[];
    const float*  Af = (const float*)Av;
    const __half* Ah = (const __half*)Av;

    const int tid  = threadIdx.x;
    const int m0   = blockIdx.y * 128;
    const int n0   = blockIdx.x * 128;
    const int wid  = tid >> 5, lane = tid & 31;
    const int wm   = wid >> 2, wn = wid & 3;        /* 2 x 4 warp grid */
    const int grp  = lane >> 2, sub = lane & 3;

    float acc[4][4][4];                             /* 64 x 32 warp tile */
    #pragma unroll
    for (int mt = 0; mt < 4; mt++)
        #pragma unroll
        for (int nt = 0; nt < 4; nt++)
            #pragma unroll
            for (int r = 0; r < 4; r++) acc[mt][nt][r] = 0.f;

    float4 areg[4];   /* AF32 staging: 16 floats / thread */

    auto cpW = [&](int kc, int buf) {
        __half* Bs = hsm + buf * STAGE_HALFS + 128 * SPADH;
        const int k0 = kc * BK;
        #pragma unroll
        for (int i = 0; i < 2; i++) {
            const int idx = tid + i * 256;          /* 0..511 */
            const int r = idx >> 2, q = idx & 3;
            cp16(Bs + r * SPADH + q * 8, W + (size_t)(n0 + r) * DIMC + k0 + q * 8);
        }
    };
    auto cpA = [&](int kc, int buf) {        /* !AF32 path */
        __half* As = hsm + buf * STAGE_HALFS;
        const int k0 = kc * BK;
        #pragma unroll
        for (int i = 0; i < 2; i++) {
            const int idx = tid + i * 256;
            const int r = idx >> 2, q = idx & 3;
            cp16(As + r * SPADH + q * 8, Ah + (size_t)(m0 + r) * DIMC + k0 + q * 8);
        }
    };
    auto ldgA = [&](int kc) {                /* AF32: gmem fp32 -> regs */
        const int k0 = kc * BK;
        #pragma unroll
        for (int i = 0; i < 4; i++) {
            const int idx = tid + i * 256;          /* 0..1023 */
            const int r = idx >> 3, q = idx & 7;    /* row, float4-slot */
            areg[i] = *reinterpret_cast<const float4*>(
                Af + (size_t)(m0 + r) * DIMC + k0 + q * 4);
        }
    };
    auto stsA = [&](int buf) {               /* regs -> half smem */
        __half* As = hsm + buf * STAGE_HALFS;
        #pragma unroll
        for (int i = 0; i < 4; i++) {
            const int idx = tid + i * 256;
            const int r = idx >> 3, q = idx & 7;
            const float4 v = areg[i];
            __half2 h0 = __floats2half2_rn(v.x, v.y);
            __half2 h1 = __floats2half2_rn(v.z, v.w);
            uint2 u;
            u.x = *(uint32_t*)&h0; u.y = *(uint32_t*)&h1;
            *reinterpret_cast<uint2*>(As + r * SPADH + q * 4) = u;
        }
    };

    /* prologue */
    if (AF32) { ldgA(0); cpW(0, 0); }
    else      { cpA(0, 0); cpW(0, 0); }
    cp_commit();

    for (int kc = 0; kc < NCHUNK; kc++) {
        cp_wait0();
        if (AF32) stsA(kc & 1);
        __syncthreads();
        if (kc + 1 < NCHUNK) {
            if (AF32) { ldgA(kc + 1); cpW(kc + 1, (kc + 1) & 1); }
            else      { cpA(kc + 1, (kc + 1) & 1); cpW(kc + 1, (kc + 1) & 1); }
            cp_commit();
        }

        const uint32_t* As = (const uint32_t*)(hsm + (kc & 1) * STAGE_HALFS);
        const uint32_t* Bs = As + 128 * SPADH / 2;

        #pragma unroll
        for (int ks = 0; ks < 2; ks++) {
            const int kkw = ks * 8;
            uint32_t a[4][4];
            #pragma unroll
            for (int mt = 0; mt < 4; mt++) {
                const uint32_t* p = As + (wm * 64 + mt * 16 + grp) * (SPADH / 2) + kkw + sub;
                a[mt][0] = p[0];
                a[mt][1] = p[8 * (SPADH / 2)];
                a[mt][2] = p[4];
                a[mt][3] = p[8 * (SPADH / 2) + 4];
            }
            #pragma unroll
            for (int nt = 0; nt < 4; nt++) {
                const uint32_t* p = Bs + (wn * 32 + nt * 8 + grp) * (SPADH / 2) + kkw + sub;
                const uint32_t b0 = p[0], b1 = p[4];
                #pragma unroll
                for (int mt = 0; mt < 4; mt++)
                    mma16(acc[mt][nt], a[mt], b0, b1);
            }
        }
        __syncthreads();
    }

    const bool do_scale = SCALE_Q && (n0 < DIMC);
    #pragma unroll
    for (int mt = 0; mt < 4; mt++) {
        const int r0 = m0 + wm * 64 + mt * 16 + grp;
        #pragma unroll
        for (int nt = 0; nt < 4; nt++) {
            const int col = n0 + wn * 32 + nt * 8 + 2 * sub;
            const float2 bv = *reinterpret_cast<const float2*>(&bias[col]);
            float2 o0 = make_float2(acc[mt][nt][0] + bv.x, acc[mt][nt][1] + bv.y);
            float2 o1 = make_float2(acc[mt][nt][2] + bv.x, acc[mt][nt][3] + bv.y);
            if (do_scale) {
                o0.x *= QK_SCALE; o0.y *= QK_SCALE;
                o1.x *= QK_SCALE; o1.y *= QK_SCALE;
            }
            *reinterpret_cast<float2*>(&C[(size_t)r0 * N + col])       = o0;
            *reinterpret_cast<float2*>(&C[(size_t)(r0 + 8) * N + col]) = o1;
        }
    }
}

/* ============================================================================ */
__global__ void cvt_f2h(const float4* __restrict__ src, __half2* __restrict__ dst, int n4)
{
    const int i = blockIdx.x * blockDim.x + threadIdx.x;
    if (i < n4) {
        const float4 v = src[i];
        dst[2 * i]     = __floats2half2_rn(v.x, v.y);
        dst[2 * i + 1] = __floats2half2_rn(v.z, v.w);
    }
}

__global__ void bias_gather(const float* __restrict__ bias_table,
                            const int* __restrict__ rel_index)
{
    const int h = blockIdx.x;
    for (int idx = threadIdx.x; idx < WIN_N * WIN_N; idx += blockDim.x)
        g_bias[h * WIN_N * WIN_N + idx] = bias_table[rel_index[idx] * NHEAD + h];
}

/* ============================================================================
 * Windowed attention, fp16 mma.sync — single-MMA QK^T and PV.
 * Error budget (measured calibration): PV-single added 2.9e-4 in quadrature
 * (R13->R15); QK-single expected ~4-5e-4 -> total ~7.8e-4 < 1e-3.
 * One block (128 thr, 4 warps) per (head, window). Softmax in registers.
 * vth written for ALL 64 seq columns (zeros beyond 49) — R14 NaN lesson.
 * ==========================================================================*/
__global__ void __launch_bounds__(128)
win_attn()
{
    extern __shared__ __align__(16) __half sm[];
    __half* qh  = sm + OFF_QH;
    __half* kh  = sm + OFF_KH;
    __half* vth = sm + OFF_VTH;
    __half* ph  = sm + OFF_PH;

    const int h = blockIdx.x;
    const int b = blockIdx.y;
    const int tid = threadIdx.x;
    const int wid = tid >> 5, lane = tid & 31;
    const int grp = lane >> 2, sub = lane & 3;

    /* ---- load q/k/v (rows padded to 64 with zeros), round to fp16 ---- */
    const float* base = g_qkv + (size_t)b * WIN_N * QKV_N + h * HD;
    #pragma unroll
    for (int i = 0; i < 16; i++) {
        const int idx = tid + i * 128;          /* 0..2047 */
        const int r = idx >> 5, d = idx & 31;
        float qv = 0.f, kv = 0.f, vv = 0.f;
        if (r < WIN_N) {
            const float* p = base + (size_t)r * QKV_N + d;
            qv = p[0]; kv = p[DIMC]; vv = p[2 * DIMC];
        }
        qh[r * AQH + d]  = __float2half_rn(qv);
        kh[r * AQH + d]  = __float2half_rn(kv);
        vth[d * AVH + r] = __float2half_rn(vv);   /* transposed; zero for r>=49 */
    }
    __syncthreads();

    /* ---- QK^T: warp w -> rows 16w..16w+15, cols 0..55 (single MMA) ---- */
    const int r0 = wid * 16;
    const int ra = r0 + grp, rb = ra + 8;
    float acc[7][4];
    #pragma unroll
    for (int nt = 0; nt < 7; nt++)
        #pragma unroll
        for (int r = 0; r < 4; r++) acc[nt][r] = 0.f;

    #pragma unroll
    for (int ks = 0; ks < 2; ks++) {            /* HD=32 -> two k16 steps */
        const int kkw = ks * 8;
        uint32_t ah[4];
        {
            const uint32_t* pH = (const uint32_t*)qh + ra * (AQH / 2) + kkw + sub;
            ah[0] = pH[0]; ah[1] = pH[8 * (AQH / 2)]; ah[2] = pH[4]; ah[3] = pH[8 * (AQH / 2) + 4];
        }
        #pragma unroll
        for (int nt = 0; nt < 7; nt++) {
            const uint32_t* bH = (const uint32_t*)kh + (nt * 8 + grp) * (AQH / 2) + kkw + sub;
            mma16(acc[nt], ah, bH[0], bH[4]);
        }
    }

    /* ---- bias add + column mask ---- */
    const float* bsrc = g_bias + h * WIN_N * WIN_N;
    #pragma unroll
    for (int nt = 0; nt < 7; nt++) {
        const int c = 8 * nt + 2 * sub;
        if (c < WIN_N) {
            if (ra < WIN_N) acc[nt][0] += bsrc[ra * WIN_N + c];
            if (rb < WIN_N) acc[nt][2] += bsrc[rb * WIN_N + c];
        } else { acc[nt][0] = -1e30f; acc[nt][2] = -1e30f; }
        if (c + 1 < WIN_N) {
            if (ra < WIN_N) acc[nt][1] += bsrc[ra * WIN_N + c + 1];
            if (rb < WIN_N) acc[nt][3] += bsrc[rb * WIN_N + c + 1];
        } else { acc[nt][1] = -1e30f; acc[nt][3] = -1e30f; }
    }

    /* ---- softmax in registers ---- */
    float mx0 = -1e30f, mx1 = -1e30f;
    #pragma unroll
    for (int nt = 0; nt < 7; nt++) {
        mx0 = fmaxf(mx0, fmaxf(acc[nt][0], acc[nt][1]));
        mx1 = fmaxf(mx1, fmaxf(acc[nt][2], acc[nt][3]));
    }
    mx0 = fmaxf(mx0, __shfl_xor_sync(0xffffffffu, mx0, 1));
    mx0 = fmaxf(mx0, __shfl_xor_sync(0xffffffffu, mx0, 2));
    mx1 = fmaxf(mx1, __shfl_xor_sync(0xffffffffu, mx1, 1));
    mx1 = fmaxf(mx1, __shfl_xor_sync(0xffffffffu, mx1, 2));
    float s0 = 0.f, s1 = 0.f;
    #pragma unroll
    for (int nt = 0; nt < 7; nt++) {
        acc[nt][0] = __expf(acc[nt][0] - mx0);
        acc[nt][1] = __expf(acc[nt][1] - mx0);
        acc[nt][2] = __expf(acc[nt][2] - mx1);
        acc[nt][3] = __expf(acc[nt][3] - mx1);
        s0 += acc[nt][0] + acc[nt][1];
        s1 += acc[nt][2] + acc[nt][3];
    }
    s0 += __shfl_xor_sync(0xffffffffu, s0, 1);
    s0 += __shfl_xor_sync(0xffffffffu, s0, 2);
    s1 += __shfl_xor_sync(0xffffffffu, s1, 1);
    s1 += __shfl_xor_sync(0xffffffffu, s1, 2);
    const float i0 = 1.f / s0, i1 = 1.f / s1;

    /* ---- store P (rows 16w..16w+15, cols 0..55) + zero cols 56..63 ---- */
    #pragma unroll
    for (int nt = 0; nt < 7; nt++) {
        const int c = 8 * nt + 2 * sub;
        ph[ra * AVH + c]     = __float2half_rn(acc[nt][0] * i0);
        ph[ra * AVH + c + 1] = __float2half_rn(acc[nt][1] * i0);
        ph[rb * AVH + c]     = __float2half_rn(acc[nt][2] * i1);
        ph[rb * AVH + c + 1] = __float2half_rn(acc[nt][3] * i1);
    }
    ((uint32_t*)ph)[ra * (AVH / 2) + 28 + sub] = 0u;
    ((uint32_t*)ph)[rb * (AVH / 2) + 28 + sub] = 0u;
    __syncwarp();   /* each warp reads back only its own 16 P rows */

    /* ---- PV: out rows 16w..16w+15, d cols 0..31, K = 64 (4 k16 steps) ---- */
    float o[4][4];
    #pragma unroll
    for (int nt = 0; nt < 4; nt++)
        #pragma unroll
        for (int r = 0; r < 4; r++) o[nt][r] = 0.f;

    #pragma unroll
    for (int ks = 0; ks < 4; ks++) {
        const int kkw = ks * 8;
        uint32_t ah[4];
        {
            const uint32_t* pH = (const uint32_t*)ph + ra * (AVH / 2) + kkw + sub;
            ah[0] = pH[0]; ah[1] = pH[8 * (AVH / 2)]; ah[2] = pH[4]; ah[3] = pH[8 * (AVH / 2) + 4];
        }
        #pragma unroll
        for (int nt = 0; nt < 4; nt++) {
            const uint32_t* bH = (const uint32_t*)vth + (nt * 8 + grp) * (AVH / 2) + kkw + sub;
            mma16(o[nt], ah, bH[0], bH[4]);
        }
    }

    /* ---- store ctx as half (feeds proj GEMM directly) ---- */
    __half* ctx = g_ctx + (size_t)b * WIN_N * DIMC + h * HD;
    #pragma unroll
    for (int nt = 0; nt < 4; nt++) {
        const int d0 = 8 * nt + 2 * sub;
        if (ra < WIN_N)
            *reinterpret_cast<__half2*>(&ctx[(size_t)ra * DIMC + d0]) =
                __floats2half2_rn(o[nt][0], o[nt][1]);
        if (rb < WIN_N)
            *reinterpret_cast<__half2*>(&ctx[(size_t)rb * DIMC + d0]) =
                __floats2half2_rn(o[nt][2], o[nt][3]);
    }
}

/* ============================================================================ */
extern "C" void kernel_launch(void* const* d_in, const int* in_sizes, int n_in,
                              void* d_out, int out_size)
{
    const float* x          = (const float*)d_in[0];
    const float* qkv_w      = (const float*)d_in[1];
    const float* qkv_b      = (const float*)d_in[2];
    const float* proj_w     = (const float*)d_in[3];
    const float* proj_b     = (const float*)d_in[4];
    const float* bias_table = (const float*)d_in[5];
    const int*   rel_index  = (const int*)d_in[6];
    float*       out        = (float*)d_out;

    float *qkv_ptr;
    __half *ctx_ptr, *wqh_ptr, *wph_ptr;
    cudaGetSymbolAddress((void**)&qkv_ptr, g_qkv);
    cudaGetSymbolAddress((void**)&ctx_ptr, g_ctx);
    cudaGetSymbolAddress((void**)&wqh_ptr, g_wqh);
    cudaGetSymbolAddress((void**)&wph_ptr, g_wph);

    cudaFuncSetAttribute(gemm_mma<QKV_N, true,  true>,  cudaFuncAttributeMaxDynamicSharedMemorySize, SMEM_DYN);
    cudaFuncSetAttribute(gemm_mma<DIMC,  false, false>, cudaFuncAttributeMaxDynamicSharedMemorySize, SMEM_DYN);
    cudaFuncSetAttribute(win_attn,                      cudaFuncAttributeMaxDynamicSharedMemorySize, SMEM_ATT);

    /* 0) weight fp16 conversion + bias gather (tiny; x cvt fused into GEMM) */
    {
        const int nq = QKV_N * DIMC / 4;
        cvt_f2h<<<(nq + 255) / 256, 256>>>((const float4*)qkv_w, (__half2*)wqh_ptr, nq);
        const int np = DIMC * DIMC / 4;
        cvt_f2h<<<(np + 255) / 256, 256>>>((const float4*)proj_w, (__half2*)wph_ptr, np);
        bias_gather<<<NHEAD, 256>>>(bias_table, rel_index);
    }

    /* 1) QKV = X * Wqkv^T + b (q pre-scaled), fp16 mma.sync, fused x->half */
    dim3 g1(QKV_N / 128, MROWS / 128);   /* (9, 1568) */
    gemm_mma<QKV_N, true, true><<<g1, 256, SMEM_DYN>>>(x, wqh_ptr, qkv_b, qkv_ptr);

    /* 2) windowed attention (single-MMA QK and PV) */
    dim3 g2(NHEAD, BWIN);                /* (12, 4096) */
    win_attn<<<g2, 128, SMEM_ATT>>>();

    /* 3) OUT = CTX * Wproj^T + b, fp16 mma.sync */
    dim3 g3(DIMC / 128, MROWS / 128);    /* (3, 1568) */
    gemm_mma<DIMC, false, false><<<g3, 256, SMEM_DYN>>>(ctx_ptr, wph_ptr, proj_b, out);
}